// round 1
// baseline (speedup 1.0000x reference)
#include <cuda_runtime.h>
#include <math.h>

// ---------------------------------------------------------------------------
// VSSBlock (VMamba) — fp32 baseline, structured for later tensor-core swap.
// Shapes: T=4,B=4 -> TB=16; H=W=56 -> L=3136; C=96; DI=192; N=16; R=6; K=4.
// ---------------------------------------------------------------------------

#define TBc   16
#define HH    56
#define WW    56
#define LL    3136            // HH*WW
#define Cc    96
#define DIc   192
#define NSc   16
#define Rc    6
#define Kc    4
#define C38   38              // R + 2N
#define M1c   (TBc*LL)        // 50176
#define MXc   (TBc*Kc*LL)     // 200704

// ------------------------- scratch (device globals) ------------------------
__device__ float g_xi  [(size_t)TBc*LL*DIc];        // (tb,l,d)  pre-conv
__device__ float g_z   [(size_t)TBc*LL*DIc];        // (tb,l,d)  gate input
__device__ float g_xsT [(size_t)TBc*Kc*LL*DIc];     // (tb,k,l,d) cross-scanned u
__device__ float g_xdbl[(size_t)TBc*Kc*LL*C38];     // (tb,k,l,38) dts|B|C
__device__ float g_delta[(size_t)TBc*Kc*LL*DIc];    // (tb,k,l,d)
__device__ float g_ysT [(size_t)TBc*Kc*LL*DIc];     // (tb,k,l,d) scan out (+D skip)
__device__ float g_y   [(size_t)TBc*LL*DIc];        // (tb,l,d) merged+LN+gated
__device__ float g_xf2 [(size_t)TBc*LL*Cc];         // (tb,l,c) after residual 1
__device__ float g_h1  [(size_t)TBc*LL*4*Cc];       // (tb,l,4C) MLP hidden

// ------------------------------- helpers -----------------------------------
__device__ __forceinline__ float siluf(float x) {
    return x / (1.0f + __expf(-x));
}
__device__ __forceinline__ float softplusf(float x) {
    float e = __expf(-fabsf(x));
    return fmaxf(x, 0.0f) + __logf(1.0f + e);
}
__device__ __forceinline__ float gelu_exactf(float x) {
    return 0.5f * x * (1.0f + erff(x * 0.70710678118654752f));
}

// ------------------------------- SGEMM --------------------------------------
// C[m,n] = sum_k A[m,k] * W[n,k];  A: MxK row-major, W: NxK row-major.
// BM=64, BN=64, BK=16, 256 threads, 4x4 micro-tile. M % 64 == 0, K % 16 == 0.
enum { EPI_INPROJ = 0, EPI_XPROJ = 1, EPI_OUTPROJ = 2, EPI_FC1 = 3, EPI_FC2 = 4 };

template <int EPI>
__global__ __launch_bounds__(256) void sgemm_kernel(
    const float* __restrict__ A, const float* __restrict__ W,
    const float* __restrict__ bias, const float* __restrict__ resid,
    float* __restrict__ out, int M, int N, int Kdim)
{
    constexpr int BM = 64, BN = 64, BK = 16;
    __shared__ float As[BK][BM + 4];
    __shared__ float Ws[BK][BN + 4];

    const int tid = threadIdx.x;
    const int m0 = blockIdx.y * BM;
    const int n0 = blockIdx.x * BN;

    const float* Wb = W;
    if (EPI == EPI_XPROJ) {
        int k = (m0 / LL) & 3;                 // tiles never cross k (3136 % 64 == 0)
        Wb = W + (size_t)k * C38 * DIc;
    }

    const int lm  = tid >> 2;                   // 0..63 (row within tile)
    const int lk4 = (tid & 3) * 4;              // 0,4,8,12 (k offset)
    const int ty  = tid >> 4;                   // 0..15
    const int tx  = tid & 15;                   // 0..15

    float acc[4][4];
#pragma unroll
    for (int i = 0; i < 4; i++)
#pragma unroll
        for (int j = 0; j < 4; j++) acc[i][j] = 0.0f;

    for (int kt = 0; kt < Kdim; kt += BK) {
        float4 av = *(const float4*)(A + (size_t)(m0 + lm) * Kdim + kt + lk4);
        As[lk4 + 0][lm] = av.x;
        As[lk4 + 1][lm] = av.y;
        As[lk4 + 2][lm] = av.z;
        As[lk4 + 3][lm] = av.w;

        float4 wv = make_float4(0.f, 0.f, 0.f, 0.f);
        int wn = n0 + lm;
        if (wn < N) wv = *(const float4*)(Wb + (size_t)wn * Kdim + kt + lk4);
        Ws[lk4 + 0][lm] = wv.x;
        Ws[lk4 + 1][lm] = wv.y;
        Ws[lk4 + 2][lm] = wv.z;
        Ws[lk4 + 3][lm] = wv.w;

        __syncthreads();
#pragma unroll
        for (int kk = 0; kk < BK; kk++) {
            float4 a = *(const float4*)&As[kk][ty * 4];
            float4 b = *(const float4*)&Ws[kk][tx * 4];
            acc[0][0] += a.x * b.x; acc[0][1] += a.x * b.y; acc[0][2] += a.x * b.z; acc[0][3] += a.x * b.w;
            acc[1][0] += a.y * b.x; acc[1][1] += a.y * b.y; acc[1][2] += a.y * b.z; acc[1][3] += a.y * b.w;
            acc[2][0] += a.z * b.x; acc[2][1] += a.z * b.y; acc[2][2] += a.z * b.z; acc[2][3] += a.z * b.w;
            acc[3][0] += a.w * b.x; acc[3][1] += a.w * b.y; acc[3][2] += a.w * b.z; acc[3][3] += a.w * b.w;
        }
        __syncthreads();
    }

#pragma unroll
    for (int i = 0; i < 4; i++) {
        int gm = m0 + ty * 4 + i;
#pragma unroll
        for (int j = 0; j < 4; j++) {
            int gn = n0 + tx * 4 + j;
            float v = acc[i][j];
            if (EPI == EPI_INPROJ) {
                if (gn < DIc)      g_xi[(size_t)gm * DIc + gn] = v;
                else               g_z [(size_t)gm * DIc + (gn - DIc)] = v;
            } else if (EPI == EPI_XPROJ) {
                if (gn < C38)      g_xdbl[(size_t)gm * C38 + gn] = v;
            } else if (EPI == EPI_OUTPROJ) {
                if (gn < Cc)       g_xf2[(size_t)gm * Cc + gn] =
                                       resid[(size_t)gm * Cc + gn] + v;
            } else if (EPI == EPI_FC1) {
                g_h1[(size_t)gm * (4 * Cc) + gn] = gelu_exactf(v + bias[gn]);
            } else if (EPI == EPI_FC2) {
                if (gn < Cc)       out[(size_t)gm * Cc + gn] =
                                       g_xf2[(size_t)gm * Cc + gn] + v + bias[gn];
            }
        }
    }
}

// --------------------- depthwise conv 3x3 + SiLU + cross-scan ---------------
// Input g_xi (tb,l,d); output: 4 scan directions into g_xsT (tb,k,l,d).
__global__ __launch_bounds__(192) void conv_scan_kernel(
    const float* __restrict__ cw, const float* __restrict__ cb)
{
    const int tb = blockIdx.x / HH;
    const int h  = blockIdx.x % HH;
    const int d  = threadIdx.x;

    float wg[9];
#pragma unroll
    for (int i = 0; i < 9; i++) wg[i] = cw[d * 9 + i];
    const float bias = cb[d];

    const float* xin = g_xi + (size_t)tb * LL * DIc + d;

    float c0[3], c1[3], c2[3];
    // column loader: rows h-1..h+1 at column wc (zero-padded)
    auto loadcol = [&](int wc, float* col) {
#pragma unroll
        for (int r = 0; r < 3; r++) {
            int hh = h - 1 + r;
            col[r] = (hh >= 0 && hh < HH && wc >= 0 && wc < WW)
                     ? xin[(size_t)(hh * WW + wc) * DIc] : 0.0f;
        }
    };
    loadcol(-1, c0);
    loadcol(0, c1);

    const size_t b = (size_t)tb * 4;
    for (int w = 0; w < WW; w++) {
        loadcol(w + 1, c2);
        float acc = bias;
        acc += c0[0] * wg[0] + c1[0] * wg[1] + c2[0] * wg[2];
        acc += c0[1] * wg[3] + c1[1] * wg[4] + c2[1] * wg[5];
        acc += c0[2] * wg[6] + c1[2] * wg[7] + c2[2] * wg[8];
        float v = siluf(acc);

        int lrm = h * WW + w;       // row-major pos
        int lcm = w * HH + h;       // col-major pos
        g_xsT[((b + 0) * LL + lrm) * DIc + d] = v;
        g_xsT[((b + 1) * LL + lcm) * DIc + d] = v;
        g_xsT[((b + 2) * LL + (LL - 1 - lrm)) * DIc + d] = v;
        g_xsT[((b + 3) * LL + (LL - 1 - lcm)) * DIc + d] = v;

        c0[0] = c1[0]; c0[1] = c1[1]; c0[2] = c1[2];
        c1[0] = c2[0]; c1[1] = c2[1]; c1[2] = c2[2];
    }
}

// --------------------- dt projection + softplus -----------------------------
// delta[tb,k,l,d] = softplus(sum_r dts[tb,k,l,r]*dtw[k,d,r] + dtb[k,d])
__global__ __launch_bounds__(192) void dt_kernel(
    const float* __restrict__ dtw, const float* __restrict__ dtb)
{
    const int tbk = blockIdx.x;            // 0..63
    const int lt  = blockIdx.y * 16;
    const int d   = threadIdx.x;
    const int k   = tbk & 3;

    float wr[6];
    const float* wp = dtw + ((size_t)k * DIc + d) * Rc;
#pragma unroll
    for (int r = 0; r < Rc; r++) wr[r] = wp[r];
    const float bias = dtb[k * DIc + d];

#pragma unroll 4
    for (int li = 0; li < 16; li++) {
        size_t row = (size_t)tbk * LL + lt + li;
        const float* xr = g_xdbl + row * C38;
        float acc = bias;
#pragma unroll
        for (int r = 0; r < Rc; r++) acc += xr[r] * wr[r];
        g_delta[row * DIc + d] = softplusf(acc);
    }
}

// ------------------------------ selective scan ------------------------------
// 4 lanes per channel, 4 states per lane. Channel = (tb,k,d). L sequential.
__global__ __launch_bounds__(256) void scan_kernel(
    const float* __restrict__ A_logs, const float* __restrict__ Ds)
{
    const int t   = blockIdx.x * 256 + threadIdx.x;
    const int c   = t >> 2;                 // channel 0..12287
    const int j   = t & 3;                  // state group
    const int tbk = c / DIc;                // 0..63
    const int d   = c - tbk * DIc;
    const int k   = tbk & 3;
    const int ad  = k * DIc + d;

    const float A0 = -expf(A_logs[ad * NSc + 4 * j + 0]);
    const float A1 = -expf(A_logs[ad * NSc + 4 * j + 1]);
    const float A2 = -expf(A_logs[ad * NSc + 4 * j + 2]);
    const float A3 = -expf(A_logs[ad * NSc + 4 * j + 3]);
    const float Dv = Ds[ad];

    const float* up = g_xsT   + (size_t)tbk * LL * DIc + d;
    const float* dp = g_delta + (size_t)tbk * LL * DIc + d;
    const float* bc = g_xdbl  + (size_t)tbk * LL * C38 + 4 * j;
    float*       yp = g_ysT   + (size_t)tbk * LL * DIc + d;

    float h0 = 0.f, h1 = 0.f, h2 = 0.f, h3 = 0.f;

    for (int l = 0; l < LL; l++) {
        float u  = up[0];
        float dt = dp[0];
        float2 B01 = *(const float2*)(bc + 6);
        float2 B23 = *(const float2*)(bc + 8);
        float2 C01 = *(const float2*)(bc + 22);
        float2 C23 = *(const float2*)(bc + 24);

        float du = dt * u;
        h0 = h0 * __expf(dt * A0) + du * B01.x;
        h1 = h1 * __expf(dt * A1) + du * B01.y;
        h2 = h2 * __expf(dt * A2) + du * B23.x;
        h3 = h3 * __expf(dt * A3) + du * B23.y;

        float acc = h0 * C01.x + h1 * C01.y + h2 * C23.x + h3 * C23.y;
        acc += __shfl_xor_sync(0xffffffffu, acc, 1);
        acc += __shfl_xor_sync(0xffffffffu, acc, 2);
        if (j == 0) yp[0] = acc + Dv * u;

        up += DIc; dp += DIc; bc += C38; yp += DIc;
    }
}

// ----------------- cross-merge + LayerNorm + SiLU gate ----------------------
__global__ __launch_bounds__(192) void merge_ln_gate_kernel(
    const float* __restrict__ ln_g, const float* __restrict__ ln_b)
{
    const int bid = blockIdx.x;
    const int tb  = bid / LL;
    const int l   = bid % LL;
    const int d   = threadIdx.x;
    const int h   = l / WW, w = l % WW;
    const int l2  = w * HH + h;

    const size_t b = (size_t)tb * 4;
    float y = g_ysT[((b + 0) * LL + l) * DIc + d]
            + g_ysT[((b + 1) * LL + l2) * DIc + d]
            + g_ysT[((b + 2) * LL + (LL - 1 - l)) * DIc + d]
            + g_ysT[((b + 3) * LL + (LL - 1 - l2)) * DIc + d];

    float s = y, s2 = y * y;
#pragma unroll
    for (int o = 16; o > 0; o >>= 1) {
        s  += __shfl_xor_sync(0xffffffffu, s,  o);
        s2 += __shfl_xor_sync(0xffffffffu, s2, o);
    }
    __shared__ float sh[14];
    const int wid = d >> 5;
    if ((d & 31) == 0) { sh[wid] = s; sh[6 + wid] = s2; }
    __syncthreads();
    if (d == 0) {
        float ts = 0.f, ts2 = 0.f;
#pragma unroll
        for (int i = 0; i < 6; i++) { ts += sh[i]; ts2 += sh[6 + i]; }
        float mu  = ts * (1.0f / 192.0f);
        float var = ts2 * (1.0f / 192.0f) - mu * mu;
        sh[12] = mu;
        sh[13] = rsqrtf(var + 1e-5f);
    }
    __syncthreads();
    float mu = sh[12], rs = sh[13];

    float yn = (y - mu) * rs * ln_g[d] + ln_b[d];
    size_t zi = ((size_t)tb * LL + l) * DIc + d;
    float zv = g_z[zi];
    g_y[zi] = yn * siluf(zv);
}

// ------------------------------- launch -------------------------------------
extern "C" void kernel_launch(void* const* d_in, const int* in_sizes, int n_in,
                              void* d_out, int out_size)
{
    const float* x          = (const float*)d_in[0];
    const float* in_proj_w  = (const float*)d_in[1];
    const float* conv_w     = (const float*)d_in[2];
    const float* conv_b     = (const float*)d_in[3];
    const float* x_proj_w   = (const float*)d_in[4];
    const float* dt_w       = (const float*)d_in[5];
    const float* dt_b       = (const float*)d_in[6];
    const float* A_logs     = (const float*)d_in[7];
    const float* Ds         = (const float*)d_in[8];
    const float* ln_g       = (const float*)d_in[9];
    const float* ln_b       = (const float*)d_in[10];
    const float* out_proj_w = (const float*)d_in[11];
    const float* fc1_w      = (const float*)d_in[12];
    const float* fc1_b      = (const float*)d_in[13];
    const float* fc2_w      = (const float*)d_in[14];
    const float* fc2_b      = (const float*)d_in[15];
    float* out = (float*)d_out;

    float *pxsT = nullptr, *py = nullptr, *pxf2 = nullptr, *ph1 = nullptr;
    cudaGetSymbolAddress((void**)&pxsT, g_xsT);
    cudaGetSymbolAddress((void**)&py,   g_y);
    cudaGetSymbolAddress((void**)&pxf2, g_xf2);
    cudaGetSymbolAddress((void**)&ph1,  g_h1);

    // 1. in_proj: (50176 x 96) @ (384 x 96)^T -> xi | z
    sgemm_kernel<EPI_INPROJ><<<dim3(384 / 64, M1c / 64), 256>>>(
        x, in_proj_w, nullptr, nullptr, nullptr, M1c, 384, Cc);

    // 2. depthwise conv + SiLU + 4-direction cross-scan
    conv_scan_kernel<<<TBc * HH, 192>>>(conv_w, conv_b);

    // 3. x_proj: per-k (50176 x 192) @ (38 x 192)^T -> dts|B|C
    sgemm_kernel<EPI_XPROJ><<<dim3(1, MXc / 64), 256>>>(
        pxsT, x_proj_w, nullptr, nullptr, nullptr, MXc, C38, DIc);

    // 4. dt projection + softplus
    dt_kernel<<<dim3(TBc * Kc, LL / 16), 192>>>(dt_w, dt_b);

    // 5. selective scan (+ D skip)
    scan_kernel<<<(TBc * Kc * DIc * 4) / 256, 256>>>(A_logs, Ds);

    // 6. cross-merge + LayerNorm + SiLU(z) gate
    merge_ln_gate_kernel<<<TBc * LL, 192>>>(ln_g, ln_b);

    // 7. out_proj + residual 1 -> g_xf2
    sgemm_kernel<EPI_OUTPROJ><<<dim3(2, M1c / 64), 256>>>(
        py, out_proj_w, nullptr, x, nullptr, M1c, Cc, DIc);

    // 8. fc1 + bias + exact GELU -> g_h1
    sgemm_kernel<EPI_FC1><<<dim3(384 / 64, M1c / 64), 256>>>(
        pxf2, fc1_w, fc1_b, nullptr, nullptr, M1c, 4 * Cc, Cc);

    // 9. fc2 + bias + residual 2 -> d_out
    sgemm_kernel<EPI_FC2><<<dim3(2, M1c / 64), 256>>>(
        ph1, fc2_w, fc2_b, nullptr, out, M1c, Cc, 4 * Cc);
}

// round 2
// speedup vs baseline: 1.4042x; 1.4042x over previous
#include <cuda_runtime.h>
#include <math.h>

// ---------------------------------------------------------------------------
// VSSBlock (VMamba) — fp32, round 2.
// Shapes: TB=16; H=W=56 -> L=3136; C=96; DI=192; N=16; R=6; K=4.
// Scratch layouts are k-major: (k, tb, l, ·) so GEMM M-tiles of 128 never
// cross a scan-direction boundary (50176 % 128 == 0 per k).
// ---------------------------------------------------------------------------

#define TBc   16
#define HH    56
#define WW    56
#define LL    3136
#define Cc    96
#define DIc   192
#define NSc   16
#define Rc    6
#define Kc    4
#define C38   38
#define M1c   (TBc*LL)        // 50176
#define MXc   (TBc*Kc*LL)     // 200704

// ------------------------- scratch (device globals) ------------------------
__device__ float g_xi  [(size_t)TBc*LL*DIc];        // (tb,l,d)  pre-conv
__device__ float g_z   [(size_t)TBc*LL*DIc];        // (tb,l,d)  gate input
__device__ float g_xsT [(size_t)Kc*TBc*LL*DIc];     // (k,tb,l,d) cross-scanned u
__device__ float g_xdbl[(size_t)Kc*TBc*LL*C38];     // (k,tb,l,38) dts|B|C
__device__ float g_delta[(size_t)Kc*TBc*LL*DIc];    // (k,tb,l,d)
__device__ float g_ysT [(size_t)Kc*TBc*LL*DIc];     // (k,tb,l,d) scan out (+D skip)
__device__ float g_y   [(size_t)TBc*LL*DIc];        // (tb,l,d) merged+LN+gated
__device__ float g_xf2 [(size_t)TBc*LL*Cc];         // (tb,l,c) after residual 1
__device__ float g_h1  [(size_t)TBc*LL*4*Cc];       // (tb,l,4C) MLP hidden

// ------------------------------- helpers -----------------------------------
__device__ __forceinline__ float siluf(float x) {
    return x / (1.0f + __expf(-x));
}
__device__ __forceinline__ float softplusf(float x) {
    float e = __expf(-fabsf(x));
    return fmaxf(x, 0.0f) + __logf(1.0f + e);
}
__device__ __forceinline__ float gelu_exactf(float x) {
    return 0.5f * x * (1.0f + erff(x * 0.70710678118654752f));
}

// ------------------------------- SGEMM --------------------------------------
// out[m,n] = sum_k A[m,k] * W[n,k];  A: MxK row-major, W: NxK row-major.
// BM=128, BN=64, BK=16, 256 threads, 8x4 micro-tile, register prefetch.
// Requires M % 128 == 0, K % 16 == 0. N guarded.
enum { EPI_INPROJ = 0, EPI_XPROJ = 1, EPI_OUTPROJ = 2, EPI_FC1 = 3, EPI_FC2 = 4 };

template <int EPI>
__global__ __launch_bounds__(256) void sgemm_kernel(
    const float* __restrict__ A, const float* __restrict__ W,
    const float* __restrict__ bias, const float* __restrict__ resid,
    float* __restrict__ out, int M, int N, int Kdim)
{
    constexpr int BM = 128, BN = 64, BK = 16;
    __shared__ float As[BK][BM + 4];
    __shared__ float Ws[BK][BN + 4];

    const int tid = threadIdx.x;
    const int m0 = blockIdx.y * BM;
    const int n0 = blockIdx.x * BN;

    size_t zbase = 0;
    const float* Wb = W;
    if (EPI == EPI_XPROJ) {                   // per-direction weights / rows
        zbase = (size_t)blockIdx.z * (size_t)M;
        Wb = W + (size_t)blockIdx.z * C38 * DIc;
    }
    const float* Ab = A + zbase * Kdim;

    // loaders: A — 2 float4 per thread; W — 1 float4 per thread
    const int lmA = tid >> 1;                 // 0..127
    const int kA  = (tid & 1) * 8;            // 0 or 8
    const int lnW = tid >> 2;                 // 0..63
    const int kW  = (tid & 3) * 4;            // 0,4,8,12

    const float* aptr = Ab + (size_t)(m0 + lmA) * Kdim + kA;
    const float* wptr = Wb + (size_t)(n0 + lnW) * Kdim + kW;
    const bool wvalid = (n0 + lnW) < N;

    float4 av0 = *(const float4*)(aptr);
    float4 av1 = *(const float4*)(aptr + 4);
    float4 wv  = wvalid ? *(const float4*)(wptr) : make_float4(0.f, 0.f, 0.f, 0.f);

    const int ty = tid >> 4;                  // 0..15 -> rows ty*8
    const int tx = tid & 15;                  // 0..15 -> cols tx*4

    float acc[8][4];
#pragma unroll
    for (int i = 0; i < 8; i++)
#pragma unroll
        for (int j = 0; j < 4; j++) acc[i][j] = 0.0f;

    for (int kt = 0; kt < Kdim; kt += BK) {
        As[kA + 0][lmA] = av0.x; As[kA + 1][lmA] = av0.y;
        As[kA + 2][lmA] = av0.z; As[kA + 3][lmA] = av0.w;
        As[kA + 4][lmA] = av1.x; As[kA + 5][lmA] = av1.y;
        As[kA + 6][lmA] = av1.z; As[kA + 7][lmA] = av1.w;
        Ws[kW + 0][lnW] = wv.x;  Ws[kW + 1][lnW] = wv.y;
        Ws[kW + 2][lnW] = wv.z;  Ws[kW + 3][lnW] = wv.w;
        __syncthreads();

        if (kt + BK < Kdim) {                 // prefetch next tile
            av0 = *(const float4*)(aptr + kt + BK);
            av1 = *(const float4*)(aptr + kt + BK + 4);
            if (wvalid) wv = *(const float4*)(wptr + kt + BK);
        }

#pragma unroll
        for (int kk = 0; kk < BK; kk++) {
            float4 a0 = *(const float4*)&As[kk][ty * 8];
            float4 a1 = *(const float4*)&As[kk][ty * 8 + 4];
            float4 b  = *(const float4*)&Ws[kk][tx * 4];
            acc[0][0] += a0.x * b.x; acc[0][1] += a0.x * b.y; acc[0][2] += a0.x * b.z; acc[0][3] += a0.x * b.w;
            acc[1][0] += a0.y * b.x; acc[1][1] += a0.y * b.y; acc[1][2] += a0.y * b.z; acc[1][3] += a0.y * b.w;
            acc[2][0] += a0.z * b.x; acc[2][1] += a0.z * b.y; acc[2][2] += a0.z * b.z; acc[2][3] += a0.z * b.w;
            acc[3][0] += a0.w * b.x; acc[3][1] += a0.w * b.y; acc[3][2] += a0.w * b.z; acc[3][3] += a0.w * b.w;
            acc[4][0] += a1.x * b.x; acc[4][1] += a1.x * b.y; acc[4][2] += a1.x * b.z; acc[4][3] += a1.x * b.w;
            acc[5][0] += a1.y * b.x; acc[5][1] += a1.y * b.y; acc[5][2] += a1.y * b.z; acc[5][3] += a1.y * b.w;
            acc[6][0] += a1.z * b.x; acc[6][1] += a1.z * b.y; acc[6][2] += a1.z * b.z; acc[6][3] += a1.z * b.w;
            acc[7][0] += a1.w * b.x; acc[7][1] += a1.w * b.y; acc[7][2] += a1.w * b.z; acc[7][3] += a1.w * b.w;
        }
        __syncthreads();
    }

#pragma unroll
    for (int i = 0; i < 8; i++) {
        const int gm = m0 + ty * 8 + i;
#pragma unroll
        for (int j = 0; j < 4; j++) {
            const int gn = n0 + tx * 4 + j;
            float v = acc[i][j];
            if (EPI == EPI_INPROJ) {
                if (gn < DIc)      g_xi[(size_t)gm * DIc + gn] = v;
                else               g_z [(size_t)gm * DIc + (gn - DIc)] = v;
            } else if (EPI == EPI_XPROJ) {
                if (gn < C38)      g_xdbl[(zbase + gm) * C38 + gn] = v;
            } else if (EPI == EPI_OUTPROJ) {
                if (gn < Cc)       g_xf2[(size_t)gm * Cc + gn] =
                                       resid[(size_t)gm * Cc + gn] + v;
            } else if (EPI == EPI_FC1) {
                g_h1[(size_t)gm * (4 * Cc) + gn] = gelu_exactf(v + bias[gn]);
            } else if (EPI == EPI_FC2) {
                if (gn < Cc)       out[(size_t)gm * Cc + gn] =
                                       g_xf2[(size_t)gm * Cc + gn] + v + bias[gn];
            }
        }
    }
}

// --------------------- depthwise conv 3x3 + SiLU + cross-scan ---------------
__global__ __launch_bounds__(192) void conv_scan_kernel(
    const float* __restrict__ cw, const float* __restrict__ cb)
{
    const int tb = blockIdx.x / HH;
    const int h  = blockIdx.x % HH;
    const int d  = threadIdx.x;

    float wg[9];
#pragma unroll
    for (int i = 0; i < 9; i++) wg[i] = cw[d * 9 + i];
    const float bias = cb[d];

    const float* xin = g_xi + (size_t)tb * LL * DIc + d;

    float c0[3], c1[3], c2[3];
    auto loadcol = [&](int wc, float* col) {
#pragma unroll
        for (int r = 0; r < 3; r++) {
            int hh = h - 1 + r;
            col[r] = (hh >= 0 && hh < HH && wc >= 0 && wc < WW)
                     ? xin[(size_t)(hh * WW + wc) * DIc] : 0.0f;
        }
    };
    loadcol(-1, c0);
    loadcol(0, c1);

    for (int w = 0; w < WW; w++) {
        loadcol(w + 1, c2);
        float acc = bias;
        acc += c0[0] * wg[0] + c1[0] * wg[1] + c2[0] * wg[2];
        acc += c0[1] * wg[3] + c1[1] * wg[4] + c2[1] * wg[5];
        acc += c0[2] * wg[6] + c1[2] * wg[7] + c2[2] * wg[8];
        float v = siluf(acc);

        int lrm = h * WW + w;       // row-major pos
        int lcm = w * HH + h;       // col-major pos
        g_xsT[((size_t)(0 * TBc + tb) * LL + lrm)            * DIc + d] = v;
        g_xsT[((size_t)(1 * TBc + tb) * LL + lcm)            * DIc + d] = v;
        g_xsT[((size_t)(2 * TBc + tb) * LL + (LL - 1 - lrm)) * DIc + d] = v;
        g_xsT[((size_t)(3 * TBc + tb) * LL + (LL - 1 - lcm)) * DIc + d] = v;

        c0[0] = c1[0]; c0[1] = c1[1]; c0[2] = c1[2];
        c1[0] = c2[0]; c1[1] = c2[1]; c1[2] = c2[2];
    }
}

// --------------------- dt projection + softplus -----------------------------
// delta[kb,l,d] = softplus(sum_r dts[kb,l,r]*dtw[k,d,r] + dtb[k,d])
// dts rows staged in smem once per 32-row block.
__global__ __launch_bounds__(192) void dt_kernel(
    const float* __restrict__ dtw, const float* __restrict__ dtb)
{
    __shared__ float sdt[32][Rc];
    const int kb = blockIdx.x;             // 0..63 (k*16+tb)
    const int k  = kb >> 4;
    const int d  = threadIdx.x;
    const size_t rowbase = (size_t)kb * LL + blockIdx.y * 32;

    {   // 32 rows x 6 = 192 loads, one per thread
        int r = d / Rc, c = d - r * Rc;
        sdt[r][c] = g_xdbl[(rowbase + r) * C38 + c];
    }

    float wr[Rc];
    const float* wp = dtw + ((size_t)k * DIc + d) * Rc;
#pragma unroll
    for (int r = 0; r < Rc; r++) wr[r] = wp[r];
    const float bias = dtb[k * DIc + d];
    __syncthreads();

#pragma unroll 4
    for (int li = 0; li < 32; li++) {
        float acc = bias;
#pragma unroll
        for (int r = 0; r < Rc; r++) acc += sdt[li][r] * wr[r];
        g_delta[(rowbase + li) * DIc + d] = softplusf(acc);
    }
}

// ------------------------------ selective scan ------------------------------
// 8 lanes per channel, 2 states per lane. Channel = (kb,d). L sequential.
__global__ __launch_bounds__(256) void scan_kernel(
    const float* __restrict__ A_logs, const float* __restrict__ Ds)
{
    const int t    = blockIdx.x * 256 + threadIdx.x;
    const int c    = t >> 3;                // channel 0..12287
    const int lane = t & 7;                 // state pair index
    const int kb   = c / DIc;               // 0..63 (k-major)
    const int d    = c - kb * DIc;
    const int k    = kb >> 4;
    const int ad   = k * DIc + d;
    const int n0   = lane * 2;

    const float A0 = -expf(A_logs[ad * NSc + n0 + 0]);
    const float A1 = -expf(A_logs[ad * NSc + n0 + 1]);
    const float Dv = Ds[ad];

    const float* up = g_xsT   + (size_t)kb * LL * DIc + d;
    const float* dp = g_delta + (size_t)kb * LL * DIc + d;
    const float* bc = g_xdbl  + (size_t)kb * LL * C38;
    float*       yp = g_ysT   + (size_t)kb * LL * DIc + d;

    float h0 = 0.f, h1 = 0.f;

    for (int l = 0; l < LL; l++) {
        float u  = up[0];
        float dt = dp[0];
        float2 B = *(const float2*)(bc + 6 + n0);
        float2 C = *(const float2*)(bc + 22 + n0);

        float du = dt * u;
        h0 = h0 * __expf(dt * A0) + du * B.x;
        h1 = h1 * __expf(dt * A1) + du * B.y;

        float acc = h0 * C.x + h1 * C.y;
        acc += __shfl_xor_sync(0xffffffffu, acc, 1);
        acc += __shfl_xor_sync(0xffffffffu, acc, 2);
        acc += __shfl_xor_sync(0xffffffffu, acc, 4);
        if (lane == 0) yp[0] = acc + Dv * u;

        up += DIc; dp += DIc; bc += C38; yp += DIc;
    }
}

// ----------------- cross-merge + LayerNorm + SiLU gate ----------------------
__global__ __launch_bounds__(192) void merge_ln_gate_kernel(
    const float* __restrict__ ln_g, const float* __restrict__ ln_b)
{
    const int bid = blockIdx.x;
    const int tb  = bid / LL;
    const int l   = bid % LL;
    const int d   = threadIdx.x;
    const int h   = l / WW, w = l % WW;
    const int l2  = w * HH + h;

    float y = g_ysT[((size_t)(0 * TBc + tb) * LL + l)            * DIc + d]
            + g_ysT[((size_t)(1 * TBc + tb) * LL + l2)           * DIc + d]
            + g_ysT[((size_t)(2 * TBc + tb) * LL + (LL - 1 - l)) * DIc + d]
            + g_ysT[((size_t)(3 * TBc + tb) * LL + (LL - 1 - l2))* DIc + d];

    float s = y, s2 = y * y;
#pragma unroll
    for (int o = 16; o > 0; o >>= 1) {
        s  += __shfl_xor_sync(0xffffffffu, s,  o);
        s2 += __shfl_xor_sync(0xffffffffu, s2, o);
    }
    __shared__ float sh[14];
    const int wid = d >> 5;
    if ((d & 31) == 0) { sh[wid] = s; sh[6 + wid] = s2; }
    __syncthreads();
    if (d == 0) {
        float ts = 0.f, ts2 = 0.f;
#pragma unroll
        for (int i = 0; i < 6; i++) { ts += sh[i]; ts2 += sh[6 + i]; }
        float mu  = ts * (1.0f / 192.0f);
        float var = ts2 * (1.0f / 192.0f) - mu * mu;
        sh[12] = mu;
        sh[13] = rsqrtf(var + 1e-5f);
    }
    __syncthreads();
    float mu = sh[12], rs = sh[13];

    float yn = (y - mu) * rs * ln_g[d] + ln_b[d];
    size_t zi = ((size_t)tb * LL + l) * DIc + d;
    float zv = g_z[zi];
    g_y[zi] = yn * siluf(zv);
}

// ------------------------------- launch -------------------------------------
extern "C" void kernel_launch(void* const* d_in, const int* in_sizes, int n_in,
                              void* d_out, int out_size)
{
    const float* x          = (const float*)d_in[0];
    const float* in_proj_w  = (const float*)d_in[1];
    const float* conv_w     = (const float*)d_in[2];
    const float* conv_b     = (const float*)d_in[3];
    const float* x_proj_w   = (const float*)d_in[4];
    const float* dt_w       = (const float*)d_in[5];
    const float* dt_b       = (const float*)d_in[6];
    const float* A_logs     = (const float*)d_in[7];
    const float* Ds         = (const float*)d_in[8];
    const float* ln_g       = (const float*)d_in[9];
    const float* ln_b       = (const float*)d_in[10];
    const float* out_proj_w = (const float*)d_in[11];
    const float* fc1_w      = (const float*)d_in[12];
    const float* fc1_b      = (const float*)d_in[13];
    const float* fc2_w      = (const float*)d_in[14];
    const float* fc2_b      = (const float*)d_in[15];
    float* out = (float*)d_out;

    float *pxsT = nullptr, *py = nullptr, *pxf2 = nullptr, *ph1 = nullptr;
    cudaGetSymbolAddress((void**)&pxsT, g_xsT);
    cudaGetSymbolAddress((void**)&py,   g_y);
    cudaGetSymbolAddress((void**)&pxf2, g_xf2);
    cudaGetSymbolAddress((void**)&ph1,  g_h1);

    // 1. in_proj: (50176 x 96) @ (384 x 96)^T -> xi | z
    sgemm_kernel<EPI_INPROJ><<<dim3(6, M1c / 128), 256>>>(
        x, in_proj_w, nullptr, nullptr, nullptr, M1c, 384, Cc);

    // 2. depthwise conv + SiLU + 4-direction cross-scan (k-major out)
    conv_scan_kernel<<<TBc * HH, 192>>>(conv_w, conv_b);

    // 3. x_proj: per-k (50176 x 192) @ (38 x 192)^T -> dts|B|C
    sgemm_kernel<EPI_XPROJ><<<dim3(1, M1c / 128, Kc), 256>>>(
        pxsT, x_proj_w, nullptr, nullptr, nullptr, M1c, C38, DIc);

    // 4. dt projection + softplus
    dt_kernel<<<dim3(TBc * Kc, LL / 32), 192>>>(dt_w, dt_b);

    // 5. selective scan (+ D skip): 8 lanes/channel x 2 states
    scan_kernel<<<(TBc * Kc * DIc * 8) / 256, 256>>>(A_logs, Ds);

    // 6. cross-merge + LayerNorm + SiLU(z) gate
    merge_ln_gate_kernel<<<TBc * LL, 192>>>(ln_g, ln_b);

    // 7. out_proj + residual 1 -> g_xf2
    sgemm_kernel<EPI_OUTPROJ><<<dim3(2, M1c / 128), 256>>>(
        py, out_proj_w, nullptr, x, nullptr, M1c, Cc, DIc);

    // 8. fc1 + bias + exact GELU -> g_h1
    sgemm_kernel<EPI_FC1><<<dim3(6, M1c / 128), 256>>>(
        pxf2, fc1_w, fc1_b, nullptr, nullptr, M1c, 4 * Cc, Cc);

    // 9. fc2 + bias + residual 2 -> d_out
    sgemm_kernel<EPI_FC2><<<dim3(2, M1c / 128), 256>>>(
        ph1, fc2_w, fc2_b, nullptr, out, M1c, Cc, 4 * Cc);
}

// round 3
// speedup vs baseline: 1.5046x; 1.0715x over previous
#include <cuda_runtime.h>
#include <math.h>
#include <stdint.h>

// ---------------------------------------------------------------------------
// VSSBlock (VMamba) — round 3: TF32 tensor-core GEMMs (mma.sync.m16n8k8).
// Shapes: TB=16; H=W=56 -> L=3136; C=96; DI=192; N=16; R=6; K=4.
// ---------------------------------------------------------------------------

#define TBc   16
#define HH    56
#define WW    56
#define LL    3136
#define Cc    96
#define DIc   192
#define NSc   16
#define Rc    6
#define Kc    4
#define C38   38
#define M1c   (TBc*LL)        // 50176
#define MXc   (TBc*Kc*LL)     // 200704

// ------------------------- scratch (device globals) ------------------------
__device__ float g_xi  [(size_t)TBc*LL*DIc];        // (tb,l,d)  pre-conv
__device__ float g_z   [(size_t)TBc*LL*DIc];        // (tb,l,d)  gate input
__device__ float g_xsT [(size_t)Kc*TBc*LL*DIc];     // (k,tb,l,d) cross-scanned u
__device__ float g_xdbl[(size_t)Kc*TBc*LL*C38];     // (k,tb,l,38) dts|B|C
__device__ float g_delta[(size_t)Kc*TBc*LL*DIc];    // (k,tb,l,d)
__device__ float g_ysT [(size_t)Kc*TBc*LL*DIc];     // (k,tb,l,d) scan out (+D skip)
__device__ float g_y   [(size_t)TBc*LL*DIc];        // (tb,l,d) merged+LN+gated
__device__ float g_xf2 [(size_t)TBc*LL*Cc];         // (tb,l,c) after residual 1
__device__ float g_h1  [(size_t)TBc*LL*4*Cc];       // (tb,l,4C) MLP hidden

// ------------------------------- helpers -----------------------------------
__device__ __forceinline__ float siluf(float x) {
    return x / (1.0f + __expf(-x));
}
__device__ __forceinline__ float softplusf(float x) {
    float e = __expf(-fabsf(x));
    return fmaxf(x, 0.0f) + __logf(1.0f + e);
}
__device__ __forceinline__ float gelu_exactf(float x) {
    return 0.5f * x * (1.0f + erff(x * 0.70710678118654752f));
}
__device__ __forceinline__ uint32_t f2tf32(float x) {
    uint32_t r;
    asm("cvt.rna.tf32.f32 %0, %1;" : "=r"(r) : "f"(x));
    return r;
}
__device__ __forceinline__ void mma_tf32(float* d, const uint32_t* a, const uint32_t* b) {
    asm volatile(
        "mma.sync.aligned.m16n8k8.row.col.f32.tf32.tf32.f32 "
        "{%0,%1,%2,%3}, {%4,%5,%6,%7}, {%8,%9}, {%0,%1,%2,%3};\n"
        : "+f"(d[0]), "+f"(d[1]), "+f"(d[2]), "+f"(d[3])
        : "r"(a[0]), "r"(a[1]), "r"(a[2]), "r"(a[3]), "r"(b[0]), "r"(b[1]));
}

// ------------------------------ TF32 GEMM -----------------------------------
// out[m,n] = sum_k A[m,k] * W[n,k];  A: MxK row-major, W: NxK row-major.
// BM=128, BN=64, BK=16, 256 threads = 8 warps (4 m x 2 n), warp tile 32x32
// via 2x4 m16n8k8 mma. smem holds tf32-converted operands.
enum { EPI_INPROJ = 0, EPI_XPROJ = 1, EPI_OUTPROJ = 2, EPI_FC1 = 3, EPI_FC2 = 4 };

template <int EPI>
__global__ __launch_bounds__(256) void mma_gemm_kernel(
    const float* __restrict__ A, const float* __restrict__ W,
    const float* __restrict__ bias, const float* __restrict__ resid,
    float* __restrict__ out, int M, int N, int Kdim)
{
    constexpr int BM = 128, BN = 64, BK = 16;
    __shared__ uint32_t As[BK][BM + 8];   // conflict-free frag loads (pad 8)
    __shared__ uint32_t Ws[BK][BN + 8];

    const int tid = threadIdx.x;
    const int m0 = blockIdx.y * BM;
    const int n0 = blockIdx.x * BN;

    size_t zbase = 0;
    const float* Wb = W;
    if (EPI == EPI_XPROJ) {                   // per-direction weights / rows
        zbase = (size_t)blockIdx.z * (size_t)M;
        Wb = W + (size_t)blockIdx.z * C38 * DIc;
    }
    const float* Ab = A + zbase * Kdim;

    // loaders: A — 2 float4 per thread; W — 1 float4 per thread
    const int lmA = tid >> 1;                 // 0..127
    const int kA  = (tid & 1) * 8;            // 0 or 8
    const int lnW = tid >> 2;                 // 0..63
    const int kW  = (tid & 3) * 4;            // 0,4,8,12

    const float* aptr = Ab + (size_t)(m0 + lmA) * Kdim + kA;
    const float* wptr = Wb + (size_t)(n0 + lnW) * Kdim + kW;
    const bool wvalid = (n0 + lnW) < N;

    float4 av0 = *(const float4*)(aptr);
    float4 av1 = *(const float4*)(aptr + 4);
    float4 wv  = wvalid ? *(const float4*)(wptr) : make_float4(0.f, 0.f, 0.f, 0.f);

    const int wid = tid >> 5;
    const int wm  = wid & 3;                  // 0..3 -> m offset wm*32
    const int wn  = wid >> 2;                 // 0..1 -> n offset wn*32
    const int lane = tid & 31;
    const int gid = lane >> 2;                // 0..7
    const int tig = lane & 3;                 // 0..3

    float acc[2][4][4];
#pragma unroll
    for (int i = 0; i < 2; i++)
#pragma unroll
        for (int j = 0; j < 4; j++)
#pragma unroll
            for (int q = 0; q < 4; q++) acc[i][j][q] = 0.0f;

    for (int kt = 0; kt < Kdim; kt += BK) {
        As[kA + 0][lmA] = f2tf32(av0.x); As[kA + 1][lmA] = f2tf32(av0.y);
        As[kA + 2][lmA] = f2tf32(av0.z); As[kA + 3][lmA] = f2tf32(av0.w);
        As[kA + 4][lmA] = f2tf32(av1.x); As[kA + 5][lmA] = f2tf32(av1.y);
        As[kA + 6][lmA] = f2tf32(av1.z); As[kA + 7][lmA] = f2tf32(av1.w);
        Ws[kW + 0][lnW] = f2tf32(wv.x);  Ws[kW + 1][lnW] = f2tf32(wv.y);
        Ws[kW + 2][lnW] = f2tf32(wv.z);  Ws[kW + 3][lnW] = f2tf32(wv.w);
        __syncthreads();

        if (kt + BK < Kdim) {                 // prefetch next tile
            av0 = *(const float4*)(aptr + kt + BK);
            av1 = *(const float4*)(aptr + kt + BK + 4);
            if (wvalid) wv = *(const float4*)(wptr + kt + BK);
        }

#pragma unroll
        for (int kc = 0; kc < BK; kc += 8) {
            uint32_t afr[2][4];
#pragma unroll
            for (int mt = 0; mt < 2; mt++) {
                const int mb = wm * 32 + mt * 16 + gid;
                afr[mt][0] = As[kc + tig    ][mb];
                afr[mt][1] = As[kc + tig    ][mb + 8];
                afr[mt][2] = As[kc + tig + 4][mb];
                afr[mt][3] = As[kc + tig + 4][mb + 8];
            }
            uint32_t bfr[4][2];
#pragma unroll
            for (int nt = 0; nt < 4; nt++) {
                const int nb = wn * 32 + nt * 8 + gid;
                bfr[nt][0] = Ws[kc + tig    ][nb];
                bfr[nt][1] = Ws[kc + tig + 4][nb];
            }
#pragma unroll
            for (int mt = 0; mt < 2; mt++)
#pragma unroll
                for (int nt = 0; nt < 4; nt++)
                    mma_tf32(acc[mt][nt], afr[mt], bfr[nt]);
        }
        __syncthreads();
    }

    // epilogue
    auto store = [&](int gm, int gn, float v) {
        if (EPI == EPI_INPROJ) {
            if (gn < DIc)      g_xi[(size_t)gm * DIc + gn] = v;
            else               g_z [(size_t)gm * DIc + (gn - DIc)] = v;
        } else if (EPI == EPI_XPROJ) {
            if (gn < C38)      g_xdbl[(zbase + gm) * C38 + gn] = v;
        } else if (EPI == EPI_OUTPROJ) {
            if (gn < Cc)       g_xf2[(size_t)gm * Cc + gn] =
                                   resid[(size_t)gm * Cc + gn] + v;
        } else if (EPI == EPI_FC1) {
            g_h1[(size_t)gm * (4 * Cc) + gn] = gelu_exactf(v + bias[gn]);
        } else if (EPI == EPI_FC2) {
            if (gn < Cc)       out[(size_t)gm * Cc + gn] =
                                   g_xf2[(size_t)gm * Cc + gn] + v + bias[gn];
        }
    };

#pragma unroll
    for (int mt = 0; mt < 2; mt++) {
        const int r0 = m0 + wm * 32 + mt * 16 + gid;
#pragma unroll
        for (int nt = 0; nt < 4; nt++) {
            const int c0 = n0 + wn * 32 + nt * 8 + 2 * tig;
            store(r0,     c0,     acc[mt][nt][0]);
            store(r0,     c0 + 1, acc[mt][nt][1]);
            store(r0 + 8, c0,     acc[mt][nt][2]);
            store(r0 + 8, c0 + 1, acc[mt][nt][3]);
        }
    }
}

// --------------------- depthwise conv 3x3 + SiLU + cross-scan ---------------
__global__ __launch_bounds__(192) void conv_scan_kernel(
    const float* __restrict__ cw, const float* __restrict__ cb)
{
    const int tb = blockIdx.x / HH;
    const int h  = blockIdx.x % HH;
    const int d  = threadIdx.x;

    float wg[9];
#pragma unroll
    for (int i = 0; i < 9; i++) wg[i] = cw[d * 9 + i];
    const float bias = cb[d];

    const float* xin = g_xi + (size_t)tb * LL * DIc + d;

    float c0[3], c1[3], c2[3];
    auto loadcol = [&](int wc, float* col) {
#pragma unroll
        for (int r = 0; r < 3; r++) {
            int hh = h - 1 + r;
            col[r] = (hh >= 0 && hh < HH && wc >= 0 && wc < WW)
                     ? xin[(size_t)(hh * WW + wc) * DIc] : 0.0f;
        }
    };
    loadcol(-1, c0);
    loadcol(0, c1);

    for (int w = 0; w < WW; w++) {
        loadcol(w + 1, c2);
        float acc = bias;
        acc += c0[0] * wg[0] + c1[0] * wg[1] + c2[0] * wg[2];
        acc += c0[1] * wg[3] + c1[1] * wg[4] + c2[1] * wg[5];
        acc += c0[2] * wg[6] + c1[2] * wg[7] + c2[2] * wg[8];
        float v = siluf(acc);

        int lrm = h * WW + w;       // row-major pos
        int lcm = w * HH + h;       // col-major pos
        g_xsT[((size_t)(0 * TBc + tb) * LL + lrm)            * DIc + d] = v;
        g_xsT[((size_t)(1 * TBc + tb) * LL + lcm)            * DIc + d] = v;
        g_xsT[((size_t)(2 * TBc + tb) * LL + (LL - 1 - lrm)) * DIc + d] = v;
        g_xsT[((size_t)(3 * TBc + tb) * LL + (LL - 1 - lcm)) * DIc + d] = v;

        c0[0] = c1[0]; c0[1] = c1[1]; c0[2] = c1[2];
        c1[0] = c2[0]; c1[1] = c2[1]; c1[2] = c2[2];
    }
}

// --------------------- dt projection + softplus -----------------------------
__global__ __launch_bounds__(192) void dt_kernel(
    const float* __restrict__ dtw, const float* __restrict__ dtb)
{
    __shared__ float sdt[32][Rc];
    const int kb = blockIdx.x;             // 0..63 (k*16+tb)
    const int k  = kb >> 4;
    const int d  = threadIdx.x;
    const size_t rowbase = (size_t)kb * LL + blockIdx.y * 32;

    {   // 32 rows x 6 = 192 loads, one per thread
        int r = d / Rc, c = d - r * Rc;
        sdt[r][c] = g_xdbl[(rowbase + r) * C38 + c];
    }

    float wr[Rc];
    const float* wp = dtw + ((size_t)k * DIc + d) * Rc;
#pragma unroll
    for (int r = 0; r < Rc; r++) wr[r] = wp[r];
    const float bias = dtb[k * DIc + d];
    __syncthreads();

#pragma unroll 4
    for (int li = 0; li < 32; li++) {
        float acc = bias;
#pragma unroll
        for (int r = 0; r < Rc; r++) acc += sdt[li][r] * wr[r];
        g_delta[(rowbase + li) * DIc + d] = softplusf(acc);
    }
}

// ------------------------------ selective scan ------------------------------
// 8 lanes per channel, 2 states per lane. Channel = (kb,d). L sequential.
__global__ __launch_bounds__(256) void scan_kernel(
    const float* __restrict__ A_logs, const float* __restrict__ Ds)
{
    const int t    = blockIdx.x * 256 + threadIdx.x;
    const int c    = t >> 3;                // channel 0..12287
    const int lane = t & 7;                 // state pair index
    const int kb   = c / DIc;               // 0..63 (k-major)
    const int d    = c - kb * DIc;
    const int k    = kb >> 4;
    const int ad   = k * DIc + d;
    const int n0   = lane * 2;

    const float A0 = -expf(A_logs[ad * NSc + n0 + 0]);
    const float A1 = -expf(A_logs[ad * NSc + n0 + 1]);
    const float Dv = Ds[ad];

    const float* up = g_xsT   + (size_t)kb * LL * DIc + d;
    const float* dp = g_delta + (size_t)kb * LL * DIc + d;
    const float* bc = g_xdbl  + (size_t)kb * LL * C38;
    float*       yp = g_ysT   + (size_t)kb * LL * DIc + d;

    float h0 = 0.f, h1 = 0.f;

    for (int l = 0; l < LL; l++) {
        float u  = up[0];
        float dt = dp[0];
        float2 B = *(const float2*)(bc + 6 + n0);
        float2 C = *(const float2*)(bc + 22 + n0);

        float du = dt * u;
        h0 = h0 * __expf(dt * A0) + du * B.x;
        h1 = h1 * __expf(dt * A1) + du * B.y;

        float acc = h0 * C.x + h1 * C.y;
        acc += __shfl_xor_sync(0xffffffffu, acc, 1);
        acc += __shfl_xor_sync(0xffffffffu, acc, 2);
        acc += __shfl_xor_sync(0xffffffffu, acc, 4);
        if (lane == 0) yp[0] = acc + Dv * u;

        up += DIc; dp += DIc; bc += C38; yp += DIc;
    }
}

// ----------------- cross-merge + LayerNorm + SiLU gate ----------------------
__global__ __launch_bounds__(192) void merge_ln_gate_kernel(
    const float* __restrict__ ln_g, const float* __restrict__ ln_b)
{
    const int bid = blockIdx.x;
    const int tb  = bid / LL;
    const int l   = bid % LL;
    const int d   = threadIdx.x;
    const int h   = l / WW, w = l % WW;
    const int l2  = w * HH + h;

    float y = g_ysT[((size_t)(0 * TBc + tb) * LL + l)            * DIc + d]
            + g_ysT[((size_t)(1 * TBc + tb) * LL + l2)           * DIc + d]
            + g_ysT[((size_t)(2 * TBc + tb) * LL + (LL - 1 - l)) * DIc + d]
            + g_ysT[((size_t)(3 * TBc + tb) * LL + (LL - 1 - l2))* DIc + d];

    float s = y, s2 = y * y;
#pragma unroll
    for (int o = 16; o > 0; o >>= 1) {
        s  += __shfl_xor_sync(0xffffffffu, s,  o);
        s2 += __shfl_xor_sync(0xffffffffu, s2, o);
    }
    __shared__ float sh[14];
    const int wid = d >> 5;
    if ((d & 31) == 0) { sh[wid] = s; sh[6 + wid] = s2; }
    __syncthreads();
    if (d == 0) {
        float ts = 0.f, ts2 = 0.f;
#pragma unroll
        for (int i = 0; i < 6; i++) { ts += sh[i]; ts2 += sh[6 + i]; }
        float mu  = ts * (1.0f / 192.0f);
        float var = ts2 * (1.0f / 192.0f) - mu * mu;
        sh[12] = mu;
        sh[13] = rsqrtf(var + 1e-5f);
    }
    __syncthreads();
    float mu = sh[12], rs = sh[13];

    float yn = (y - mu) * rs * ln_g[d] + ln_b[d];
    size_t zi = ((size_t)tb * LL + l) * DIc + d;
    float zv = g_z[zi];
    g_y[zi] = yn * siluf(zv);
}

// ------------------------------- launch -------------------------------------
extern "C" void kernel_launch(void* const* d_in, const int* in_sizes, int n_in,
                              void* d_out, int out_size)
{
    const float* x          = (const float*)d_in[0];
    const float* in_proj_w  = (const float*)d_in[1];
    const float* conv_w     = (const float*)d_in[2];
    const float* conv_b     = (const float*)d_in[3];
    const float* x_proj_w   = (const float*)d_in[4];
    const float* dt_w       = (const float*)d_in[5];
    const float* dt_b       = (const float*)d_in[6];
    const float* A_logs     = (const float*)d_in[7];
    const float* Ds         = (const float*)d_in[8];
    const float* ln_g       = (const float*)d_in[9];
    const float* ln_b       = (const float*)d_in[10];
    const float* out_proj_w = (const float*)d_in[11];
    const float* fc1_w      = (const float*)d_in[12];
    const float* fc1_b      = (const float*)d_in[13];
    const float* fc2_w      = (const float*)d_in[14];
    const float* fc2_b      = (const float*)d_in[15];
    float* out = (float*)d_out;

    float *pxsT = nullptr, *py = nullptr, *pxf2 = nullptr, *ph1 = nullptr;
    cudaGetSymbolAddress((void**)&pxsT, g_xsT);
    cudaGetSymbolAddress((void**)&py,   g_y);
    cudaGetSymbolAddress((void**)&pxf2, g_xf2);
    cudaGetSymbolAddress((void**)&ph1,  g_h1);

    // 1. in_proj: (50176 x 96) @ (384 x 96)^T -> xi | z
    mma_gemm_kernel<EPI_INPROJ><<<dim3(6, M1c / 128), 256>>>(
        x, in_proj_w, nullptr, nullptr, nullptr, M1c, 384, Cc);

    // 2. depthwise conv + SiLU + 4-direction cross-scan (k-major out)
    conv_scan_kernel<<<TBc * HH, 192>>>(conv_w, conv_b);

    // 3. x_proj: per-k (50176 x 192) @ (38 x 192)^T -> dts|B|C
    mma_gemm_kernel<EPI_XPROJ><<<dim3(1, M1c / 128, Kc), 256>>>(
        pxsT, x_proj_w, nullptr, nullptr, nullptr, M1c, C38, DIc);

    // 4. dt projection + softplus
    dt_kernel<<<dim3(TBc * Kc, LL / 32), 192>>>(dt_w, dt_b);

    // 5. selective scan (+ D skip): 8 lanes/channel x 2 states
    scan_kernel<<<(TBc * Kc * DIc * 8) / 256, 256>>>(A_logs, Ds);

    // 6. cross-merge + LayerNorm + SiLU(z) gate
    merge_ln_gate_kernel<<<TBc * LL, 192>>>(ln_g, ln_b);

    // 7. out_proj + residual 1 -> g_xf2
    mma_gemm_kernel<EPI_OUTPROJ><<<dim3(2, M1c / 128), 256>>>(
        py, out_proj_w, nullptr, x, nullptr, M1c, Cc, DIc);

    // 8. fc1 + bias + exact GELU -> g_h1
    mma_gemm_kernel<EPI_FC1><<<dim3(6, M1c / 128), 256>>>(
        pxf2, fc1_w, fc1_b, nullptr, nullptr, M1c, 4 * Cc, Cc);

    // 9. fc2 + bias + residual 2 -> d_out
    mma_gemm_kernel<EPI_FC2><<<dim3(2, M1c / 128), 256>>>(
        ph1, fc2_w, fc2_b, nullptr, out, M1c, Cc, 4 * Cc);
}

// round 4
// speedup vs baseline: 1.8117x; 1.2041x over previous
#include <cuda_runtime.h>
#include <math.h>
#include <stdint.h>

// ---------------------------------------------------------------------------
// VSSBlock (VMamba) — round 4: fused-dt selective scan with exp->power chain,
// 2-direction storage (reversed reads), TF32 tensor-core GEMMs.
// Shapes: TB=16; H=W=56 -> L=3136; C=96; DI=192; N=16; R=6; K=4.
// ---------------------------------------------------------------------------

#define TBc   16
#define HH    56
#define WW    56
#define LL    3136
#define Cc    96
#define DIc   192
#define NSc   16
#define Rc    6
#define Kc    4
#define C38   38
#define M1c   (TBc*LL)        // 50176

// ------------------------- scratch (device globals) ------------------------
__device__ float g_xi  [(size_t)TBc*LL*DIc];        // (tb,l,d)  pre-conv
__device__ float g_z   [(size_t)TBc*LL*DIc];        // (tb,l,d)  gate input
__device__ float g_xs2 [(size_t)2*TBc*LL*DIc];      // (k2,tb,l,d) dirs 0,1 only
__device__ float g_xdbl[(size_t)Kc*TBc*LL*C38];     // (k,tb,l,38) dts|B|C
__device__ float g_ysT [(size_t)Kc*TBc*LL*DIc];     // (k,tb,l,d) scan out (+D skip)
__device__ float g_y   [(size_t)TBc*LL*DIc];        // (tb,l,d) merged+LN+gated
__device__ float g_xf2 [(size_t)TBc*LL*Cc];         // (tb,l,c) after residual 1
__device__ float g_h1  [(size_t)TBc*LL*4*Cc];       // (tb,l,4C) MLP hidden

// ------------------------------- helpers -----------------------------------
__device__ __forceinline__ float siluf(float x) {
    return x / (1.0f + __expf(-x));
}
__device__ __forceinline__ float gelu_exactf(float x) {
    return 0.5f * x * (1.0f + erff(x * 0.70710678118654752f));
}
__device__ __forceinline__ uint32_t f2tf32(float x) {
    uint32_t r;
    asm("cvt.rna.tf32.f32 %0, %1;" : "=r"(r) : "f"(x));
    return r;
}
__device__ __forceinline__ void mma_tf32(float* d, const uint32_t* a, const uint32_t* b) {
    asm volatile(
        "mma.sync.aligned.m16n8k8.row.col.f32.tf32.tf32.f32 "
        "{%0,%1,%2,%3}, {%4,%5,%6,%7}, {%8,%9}, {%0,%1,%2,%3};\n"
        : "+f"(d[0]), "+f"(d[1]), "+f"(d[2]), "+f"(d[3])
        : "r"(a[0]), "r"(a[1]), "r"(a[2]), "r"(a[3]), "r"(b[0]), "r"(b[1]));
}

// ------------------------------ TF32 GEMM -----------------------------------
// out[m,n] = sum_k A[m,k] * W[n,k];  A: MxK row-major, W: NxK row-major.
// BM=128, BN=64, BK=16, 256 threads = 8 warps (4m x 2n), warp tile 32x32.
enum { EPI_INPROJ = 0, EPI_XPROJ = 1, EPI_OUTPROJ = 2, EPI_FC1 = 3, EPI_FC2 = 4 };

template <int EPI>
__global__ __launch_bounds__(256) void mma_gemm_kernel(
    const float* __restrict__ A, const float* __restrict__ W,
    const float* __restrict__ bias, const float* __restrict__ resid,
    float* __restrict__ out, int M, int N, int Kdim)
{
    constexpr int BM = 128, BN = 64, BK = 16;
    __shared__ uint32_t As[BK][BM + 8];
    __shared__ uint32_t Ws[BK][BN + 8];

    const int tid = threadIdx.x;
    const int m0 = blockIdx.y * BM;
    const int n0 = blockIdx.x * BN;

    size_t zbase = 0;
    const float* Wb = W;
    const float* Ab = A;
    if (EPI == EPI_XPROJ) {                   // per-direction weights / rows
        const int kz = blockIdx.z;
        zbase = (size_t)kz * (size_t)M;
        Wb = W + (size_t)kz * C38 * DIc;
        Ab = A + (size_t)((kz < 2) ? kz : (kz - 2)) * (size_t)M * Kdim;
    }

    // loaders: A — 2 float4 per thread; W — 1 float4 per thread
    const int lmA = tid >> 1;                 // 0..127
    const int kA  = (tid & 1) * 8;            // 0 or 8
    const int lnW = tid >> 2;                 // 0..63
    const int kW  = (tid & 3) * 4;            // 0,4,8,12

    int srow = m0 + lmA;
    if (EPI == EPI_XPROJ && blockIdx.z >= 2) {
        // directions 2/3 read directions 0/1 reversed per-image
        int tb = srow / LL;
        int l  = srow - tb * LL;
        srow = tb * LL + (LL - 1 - l);
    }
    const float* aptr = Ab + (size_t)srow * Kdim + kA;
    const float* wptr = Wb + (size_t)(n0 + lnW) * Kdim + kW;
    const bool wvalid = (n0 + lnW) < N;

    float4 av0 = *(const float4*)(aptr);
    float4 av1 = *(const float4*)(aptr + 4);
    float4 wv  = wvalid ? *(const float4*)(wptr) : make_float4(0.f, 0.f, 0.f, 0.f);

    const int wid = tid >> 5;
    const int wm  = wid & 3;                  // m offset wm*32
    const int wn  = wid >> 2;                 // n offset wn*32
    const int lane = tid & 31;
    const int gid = lane >> 2;                // 0..7
    const int tig = lane & 3;                 // 0..3

    float acc[2][4][4];
#pragma unroll
    for (int i = 0; i < 2; i++)
#pragma unroll
        for (int j = 0; j < 4; j++)
#pragma unroll
            for (int q = 0; q < 4; q++) acc[i][j][q] = 0.0f;

    for (int kt = 0; kt < Kdim; kt += BK) {
        As[kA + 0][lmA] = f2tf32(av0.x); As[kA + 1][lmA] = f2tf32(av0.y);
        As[kA + 2][lmA] = f2tf32(av0.z); As[kA + 3][lmA] = f2tf32(av0.w);
        As[kA + 4][lmA] = f2tf32(av1.x); As[kA + 5][lmA] = f2tf32(av1.y);
        As[kA + 6][lmA] = f2tf32(av1.z); As[kA + 7][lmA] = f2tf32(av1.w);
        Ws[kW + 0][lnW] = f2tf32(wv.x);  Ws[kW + 1][lnW] = f2tf32(wv.y);
        Ws[kW + 2][lnW] = f2tf32(wv.z);  Ws[kW + 3][lnW] = f2tf32(wv.w);
        __syncthreads();

        if (kt + BK < Kdim) {
            av0 = *(const float4*)(aptr + kt + BK);
            av1 = *(const float4*)(aptr + kt + BK + 4);
            if (wvalid) wv = *(const float4*)(wptr + kt + BK);
        }

#pragma unroll
        for (int kc = 0; kc < BK; kc += 8) {
            uint32_t afr[2][4];
#pragma unroll
            for (int mt = 0; mt < 2; mt++) {
                const int mb = wm * 32 + mt * 16 + gid;
                afr[mt][0] = As[kc + tig    ][mb];
                afr[mt][1] = As[kc + tig    ][mb + 8];
                afr[mt][2] = As[kc + tig + 4][mb];
                afr[mt][3] = As[kc + tig + 4][mb + 8];
            }
            uint32_t bfr[4][2];
#pragma unroll
            for (int nt = 0; nt < 4; nt++) {
                const int nb = wn * 32 + nt * 8 + gid;
                bfr[nt][0] = Ws[kc + tig    ][nb];
                bfr[nt][1] = Ws[kc + tig + 4][nb];
            }
#pragma unroll
            for (int mt = 0; mt < 2; mt++)
#pragma unroll
                for (int nt = 0; nt < 4; nt++)
                    mma_tf32(acc[mt][nt], afr[mt], bfr[nt]);
        }
        __syncthreads();
    }

    auto store = [&](int gm, int gn, float v) {
        if (EPI == EPI_INPROJ) {
            if (gn < DIc)      g_xi[(size_t)gm * DIc + gn] = v;
            else               g_z [(size_t)gm * DIc + (gn - DIc)] = v;
        } else if (EPI == EPI_XPROJ) {
            if (gn < C38)      g_xdbl[(zbase + gm) * C38 + gn] = v;
        } else if (EPI == EPI_OUTPROJ) {
            if (gn < Cc)       g_xf2[(size_t)gm * Cc + gn] =
                                   resid[(size_t)gm * Cc + gn] + v;
        } else if (EPI == EPI_FC1) {
            g_h1[(size_t)gm * (4 * Cc) + gn] = gelu_exactf(v + bias[gn]);
        } else if (EPI == EPI_FC2) {
            if (gn < Cc)       out[(size_t)gm * Cc + gn] =
                                   g_xf2[(size_t)gm * Cc + gn] + v + bias[gn];
        }
    };

#pragma unroll
    for (int mt = 0; mt < 2; mt++) {
        const int r0 = m0 + wm * 32 + mt * 16 + gid;
#pragma unroll
        for (int nt = 0; nt < 4; nt++) {
            const int c0 = n0 + wn * 32 + nt * 8 + 2 * tig;
            store(r0,     c0,     acc[mt][nt][0]);
            store(r0,     c0 + 1, acc[mt][nt][1]);
            store(r0 + 8, c0,     acc[mt][nt][2]);
            store(r0 + 8, c0 + 1, acc[mt][nt][3]);
        }
    }
}

// --------------------- depthwise conv 3x3 + SiLU + cross-scan ---------------
// Writes only dirs 0 (row-major) and 1 (col-major); dirs 2/3 are read reversed.
__global__ __launch_bounds__(192) void conv_scan_kernel(
    const float* __restrict__ cw, const float* __restrict__ cb)
{
    const int tb = blockIdx.x / HH;
    const int h  = blockIdx.x % HH;
    const int d  = threadIdx.x;

    float wg[9];
#pragma unroll
    for (int i = 0; i < 9; i++) wg[i] = cw[d * 9 + i];
    const float bias = cb[d];

    const float* xin = g_xi + (size_t)tb * LL * DIc + d;

    float c0[3], c1[3], c2[3];
    auto loadcol = [&](int wc, float* col) {
#pragma unroll
        for (int r = 0; r < 3; r++) {
            int hh = h - 1 + r;
            col[r] = (hh >= 0 && hh < HH && wc >= 0 && wc < WW)
                     ? xin[(size_t)(hh * WW + wc) * DIc] : 0.0f;
        }
    };
    loadcol(-1, c0);
    loadcol(0, c1);

    for (int w = 0; w < WW; w++) {
        loadcol(w + 1, c2);
        float acc = bias;
        acc += c0[0] * wg[0] + c1[0] * wg[1] + c2[0] * wg[2];
        acc += c0[1] * wg[3] + c1[1] * wg[4] + c2[1] * wg[5];
        acc += c0[2] * wg[6] + c1[2] * wg[7] + c2[2] * wg[8];
        float v = siluf(acc);

        int lrm = h * WW + w;       // row-major pos
        int lcm = w * HH + h;       // col-major pos
        g_xs2[((size_t)(0 * TBc + tb) * LL + lrm) * DIc + d] = v;
        g_xs2[((size_t)(1 * TBc + tb) * LL + lcm) * DIc + d] = v;

        c0[0] = c1[0]; c0[1] = c1[1]; c0[2] = c1[2];
        c1[0] = c2[0]; c1[1] = c2[1]; c1[2] = c2[2];
    }
}

// ------------------------------ selective scan ------------------------------
// Fused dt-projection + softplus + scan + D skip.
// 4 lanes per channel, 4 states per lane. Channel = (kb, d).
// exp(dt*A_n) computed as r^n with r = exp(-dt) when A matches -(1..16)
// (runtime-checked), else honest __expf fallback.
__global__ __launch_bounds__(256) void scan_kernel(
    const float* __restrict__ A_logs, const float* __restrict__ Ds,
    const float* __restrict__ dtw, const float* __restrict__ dtb)
{
    const int t  = blockIdx.x * 256 + threadIdx.x;
    const int c  = t >> 2;                 // channel 0..12287
    const int j  = t & 3;                  // state quad index
    const int kb = c / DIc;                // 0..63 (k-major)
    const int d  = c - kb * DIc;
    const int kz = kb >> 4;
    const int tb = kb & 15;
    const int ad = kz * DIc + d;
    const int n0 = 4 * j;

    float Aq[4];
#pragma unroll
    for (int i = 0; i < 4; i++) Aq[i] = -expf(A_logs[ad * NSc + n0 + i]);
    bool pw = true;
#pragma unroll
    for (int i = 0; i < 4; i++)
        pw = pw && (fabsf(Aq[i] + (float)(n0 + i + 1)) < 1e-5f);
    const bool pow_ok = __all_sync(0xffffffffu, pw);

    const float Dv = Ds[ad];

    float wr[Rc];
    const float* wp = dtw + ((size_t)kz * DIc + d) * Rc;
#pragma unroll
    for (int r = 0; r < Rc; r++) wr[r] = wp[r];
    const float dbias = dtb[kz * DIc + d];

    const float* up;
    int ustride;
    if (kz < 2) {
        up = g_xs2 + (size_t)(kz * TBc + tb) * LL * DIc + d;
        ustride = DIc;
    } else {
        up = g_xs2 + ((size_t)((kz - 2) * TBc + tb) * LL + (LL - 1)) * DIc + d;
        ustride = -DIc;
    }
    const float* rowp = g_xdbl + (size_t)kb * LL * C38;
    float*       yp   = g_ysT  + (size_t)kb * LL * DIc + d;

    float h0 = 0.f, h1 = 0.f, h2 = 0.f, h3 = 0.f;

    // software-pipelined loads (1 step ahead)
    float  u_c  = up[0];
    float2 x01  = *(const float2*)(rowp + 0);
    float2 x23  = *(const float2*)(rowp + 2);
    float2 x45  = *(const float2*)(rowp + 4);
    float2 B01  = *(const float2*)(rowp + 6 + n0);
    float2 B23  = *(const float2*)(rowp + 8 + n0);
    float2 C01  = *(const float2*)(rowp + 22 + n0);
    float2 C23  = *(const float2*)(rowp + 24 + n0);

    for (int l = 0; l < LL; l++) {
        float  u_n = 0.f;
        float2 nx01, nx23, nx45, nB01, nB23, nC01, nC23;
        if (l + 1 < LL) {
            const float* nr = rowp + C38;
            u_n  = up[ustride];
            nx01 = *(const float2*)(nr + 0);
            nx23 = *(const float2*)(nr + 2);
            nx45 = *(const float2*)(nr + 4);
            nB01 = *(const float2*)(nr + 6 + n0);
            nB23 = *(const float2*)(nr + 8 + n0);
            nC01 = *(const float2*)(nr + 22 + n0);
            nC23 = *(const float2*)(nr + 24 + n0);
        } else {
            nx01 = nx23 = nx45 = nB01 = nB23 = nC01 = nC23 = make_float2(0.f, 0.f);
        }

        // dt projection + softplus (+ r = exp(-dt) shared with softplus)
        float xv = dbias;
        xv = fmaf(x01.x, wr[0], xv); xv = fmaf(x01.y, wr[1], xv);
        xv = fmaf(x23.x, wr[2], xv); xv = fmaf(x23.y, wr[3], xv);
        xv = fmaf(x45.x, wr[4], xv); xv = fmaf(x45.y, wr[5], xv);

        float dt, r;
        if (xv > 20.0f) {                 // softplus(x) ~= x
            dt = xv;
            r  = __expf(-xv);
        } else {
            float e = __expf(xv);
            r  = __fdividef(1.0f, 1.0f + e);   // exp(-softplus(x))
            dt = __logf(1.0f + e);
        }

        float e0, e1, e2, e3;
        if (pow_ok) {
            float r2 = r * r, r4 = r2 * r2;
            float base = (j == 0) ? 1.0f
                       : (j == 1) ? r4
                       : (j == 2) ? r4 * r4
                                  : r4 * r4 * r4;
            e0 = base * r; e1 = e0 * r; e2 = e1 * r; e3 = e2 * r;
        } else {
            e0 = __expf(dt * Aq[0]); e1 = __expf(dt * Aq[1]);
            e2 = __expf(dt * Aq[2]); e3 = __expf(dt * Aq[3]);
        }

        float du = dt * u_c;
        h0 = fmaf(h0, e0, du * B01.x);
        h1 = fmaf(h1, e1, du * B01.y);
        h2 = fmaf(h2, e2, du * B23.x);
        h3 = fmaf(h3, e3, du * B23.y);

        float acc = h0 * C01.x + h1 * C01.y + h2 * C23.x + h3 * C23.y;
        acc += __shfl_xor_sync(0xffffffffu, acc, 1);
        acc += __shfl_xor_sync(0xffffffffu, acc, 2);
        if (j == 0) yp[0] = acc + Dv * u_c;

        u_c = u_n;
        x01 = nx01; x23 = nx23; x45 = nx45;
        B01 = nB01; B23 = nB23; C01 = nC01; C23 = nC23;
        up += ustride; rowp += C38; yp += DIc;
    }
}

// ----------------- cross-merge + LayerNorm + SiLU gate ----------------------
__global__ __launch_bounds__(192) void merge_ln_gate_kernel(
    const float* __restrict__ ln_g, const float* __restrict__ ln_b)
{
    const int bid = blockIdx.x;
    const int tb  = bid / LL;
    const int l   = bid % LL;
    const int d   = threadIdx.x;
    const int h   = l / WW, w = l % WW;
    const int l2  = w * HH + h;

    float y = g_ysT[((size_t)(0 * TBc + tb) * LL + l)             * DIc + d]
            + g_ysT[((size_t)(1 * TBc + tb) * LL + l2)            * DIc + d]
            + g_ysT[((size_t)(2 * TBc + tb) * LL + (LL - 1 - l))  * DIc + d]
            + g_ysT[((size_t)(3 * TBc + tb) * LL + (LL - 1 - l2)) * DIc + d];

    float s = y, s2 = y * y;
#pragma unroll
    for (int o = 16; o > 0; o >>= 1) {
        s  += __shfl_xor_sync(0xffffffffu, s,  o);
        s2 += __shfl_xor_sync(0xffffffffu, s2, o);
    }
    __shared__ float sh[14];
    const int wid = d >> 5;
    if ((d & 31) == 0) { sh[wid] = s; sh[6 + wid] = s2; }
    __syncthreads();
    if (d == 0) {
        float ts = 0.f, ts2 = 0.f;
#pragma unroll
        for (int i = 0; i < 6; i++) { ts += sh[i]; ts2 += sh[6 + i]; }
        float mu  = ts * (1.0f / 192.0f);
        float var = ts2 * (1.0f / 192.0f) - mu * mu;
        sh[12] = mu;
        sh[13] = rsqrtf(var + 1e-5f);
    }
    __syncthreads();
    float mu = sh[12], rs = sh[13];

    float yn = (y - mu) * rs * ln_g[d] + ln_b[d];
    size_t zi = ((size_t)tb * LL + l) * DIc + d;
    float zv = g_z[zi];
    g_y[zi] = yn * siluf(zv);
}

// ------------------------------- launch -------------------------------------
extern "C" void kernel_launch(void* const* d_in, const int* in_sizes, int n_in,
                              void* d_out, int out_size)
{
    const float* x          = (const float*)d_in[0];
    const float* in_proj_w  = (const float*)d_in[1];
    const float* conv_w     = (const float*)d_in[2];
    const float* conv_b     = (const float*)d_in[3];
    const float* x_proj_w   = (const float*)d_in[4];
    const float* dt_w       = (const float*)d_in[5];
    const float* dt_b       = (const float*)d_in[6];
    const float* A_logs     = (const float*)d_in[7];
    const float* Ds         = (const float*)d_in[8];
    const float* ln_g       = (const float*)d_in[9];
    const float* ln_b       = (const float*)d_in[10];
    const float* out_proj_w = (const float*)d_in[11];
    const float* fc1_w      = (const float*)d_in[12];
    const float* fc1_b      = (const float*)d_in[13];
    const float* fc2_w      = (const float*)d_in[14];
    const float* fc2_b      = (const float*)d_in[15];
    float* out = (float*)d_out;

    float *pxs2 = nullptr, *py = nullptr, *pxf2 = nullptr, *ph1 = nullptr;
    cudaGetSymbolAddress((void**)&pxs2, g_xs2);
    cudaGetSymbolAddress((void**)&py,   g_y);
    cudaGetSymbolAddress((void**)&pxf2, g_xf2);
    cudaGetSymbolAddress((void**)&ph1,  g_h1);

    // 1. in_proj: (50176 x 96) @ (384 x 96)^T -> xi | z
    mma_gemm_kernel<EPI_INPROJ><<<dim3(6, M1c / 128), 256>>>(
        x, in_proj_w, nullptr, nullptr, nullptr, M1c, 384, Cc);

    // 2. depthwise conv + SiLU + cross-scan (dirs 0,1 only)
    conv_scan_kernel<<<TBc * HH, 192>>>(conv_w, conv_b);

    // 3. x_proj: per-direction (50176 x 192) @ (38 x 192)^T -> dts|B|C
    //    dirs 2,3 read dirs 0,1 reversed per image.
    mma_gemm_kernel<EPI_XPROJ><<<dim3(1, M1c / 128, Kc), 256>>>(
        pxs2, x_proj_w, nullptr, nullptr, nullptr, M1c, C38, DIc);

    // 4. fused dt-proj + softplus + selective scan (+ D skip)
    scan_kernel<<<(TBc * Kc * DIc * 4) / 256, 256>>>(A_logs, Ds, dt_w, dt_b);

    // 5. cross-merge + LayerNorm + SiLU(z) gate
    merge_ln_gate_kernel<<<TBc * LL, 192>>>(ln_g, ln_b);

    // 6. out_proj + residual 1 -> g_xf2
    mma_gemm_kernel<EPI_OUTPROJ><<<dim3(2, M1c / 128), 256>>>(
        py, out_proj_w, nullptr, x, nullptr, M1c, Cc, DIc);

    // 7. fc1 + bias + exact GELU -> g_h1
    mma_gemm_kernel<EPI_FC1><<<dim3(6, M1c / 128), 256>>>(
        pxf2, fc1_w, fc1_b, nullptr, nullptr, M1c, 4 * Cc, Cc);

    // 8. fc2 + bias + residual 2 -> d_out
    mma_gemm_kernel<EPI_FC2><<<dim3(2, M1c / 128), 256>>>(
        ph1, fc2_w, fc2_b, nullptr, out, M1c, Cc, 4 * Cc);
}

// round 5
// speedup vs baseline: 2.2405x; 1.2367x over previous
#include <cuda_runtime.h>
#include <math.h>
#include <stdint.h>

// ---------------------------------------------------------------------------
// VSSBlock (VMamba) — round 5: CHUNKED selective scan (16 segments of 196),
// fused dt, exp->power chain, 2-direction storage, TF32 tensor-core GEMMs.
// Shapes: TB=16; H=W=56 -> L=3136; C=96; DI=192; N=16; R=6; K=4.
// ---------------------------------------------------------------------------

#define TBc   16
#define HH    56
#define WW    56
#define LL    3136
#define Cc    96
#define DIc   192
#define NSc   16
#define Rc    6
#define Kc    4
#define C38   38
#define M1c   (TBc*LL)        // 50176
#define SEG   196
#define NSEG  16
#define NCH   (TBc*Kc*DIc)    // 12288 channels

// ------------------------- scratch (device globals) ------------------------
__device__ float g_xi  [(size_t)TBc*LL*DIc];        // (tb,l,d)  pre-conv
__device__ float g_z   [(size_t)TBc*LL*DIc];        // (tb,l,d)  gate input
__device__ float g_xs2 [(size_t)2*TBc*LL*DIc];      // (k2,tb,l,d) dirs 0,1 only
__device__ float g_xdbl[(size_t)Kc*TBc*LL*C38];     // (k,tb,pos,38) dts|B|C
__device__ float g_ysT [(size_t)Kc*TBc*LL*DIc];     // (k,tb,pos,d) scan out
__device__ float g_y   [(size_t)TBc*LL*DIc];        // (tb,l,d) merged+LN+gated
__device__ float g_xf2 [(size_t)TBc*LL*Cc];         // (tb,l,c) after residual 1
__device__ float g_h1  [(size_t)TBc*LL*4*Cc];       // (tb,l,4C) MLP hidden
__device__ float g_hend[(size_t)NCH*NSEG*NSc];      // (c,seg,n) local end state
__device__ float g_Eend[(size_t)NCH*NSEG*NSc];      // (c,seg,n) decay product
__device__ float g_h0  [(size_t)NCH*NSEG*NSc];      // (c,seg,n) segment start state

// ------------------------------- helpers -----------------------------------
__device__ __forceinline__ float siluf(float x) {
    return x / (1.0f + __expf(-x));
}
__device__ __forceinline__ float gelu_exactf(float x) {
    return 0.5f * x * (1.0f + erff(x * 0.70710678118654752f));
}
__device__ __forceinline__ uint32_t f2tf32(float x) {
    uint32_t r;
    asm("cvt.rna.tf32.f32 %0, %1;" : "=r"(r) : "f"(x));
    return r;
}
__device__ __forceinline__ void mma_tf32(float* d, const uint32_t* a, const uint32_t* b) {
    asm volatile(
        "mma.sync.aligned.m16n8k8.row.col.f32.tf32.tf32.f32 "
        "{%0,%1,%2,%3}, {%4,%5,%6,%7}, {%8,%9}, {%0,%1,%2,%3};\n"
        : "+f"(d[0]), "+f"(d[1]), "+f"(d[2]), "+f"(d[3])
        : "r"(a[0]), "r"(a[1]), "r"(a[2]), "r"(a[3]), "r"(b[0]), "r"(b[1]));
}

// shared per-step math: dt projection + softplus + decay factors
struct StepDecay {
    float dt, e0, e1, e2, e3;
};
__device__ __forceinline__ StepDecay step_decay(
    float2 x01, float2 x23, float2 x45,
    const float* wr, float dbias, bool pow_ok, int j, const float* Aq)
{
    float xv = dbias;
    xv = fmaf(x01.x, wr[0], xv); xv = fmaf(x01.y, wr[1], xv);
    xv = fmaf(x23.x, wr[2], xv); xv = fmaf(x23.y, wr[3], xv);
    xv = fmaf(x45.x, wr[4], xv); xv = fmaf(x45.y, wr[5], xv);

    float dt, r;
    if (xv > 20.0f) {
        dt = xv;
        r  = __expf(-xv);
    } else {
        float e = __expf(xv);
        r  = __fdividef(1.0f, 1.0f + e);   // exp(-softplus(x))
        dt = __logf(1.0f + e);
    }

    StepDecay s;
    s.dt = dt;
    if (pow_ok) {
        float r2 = r * r, r4 = r2 * r2;
        float base = (j == 0) ? 1.0f
                   : (j == 1) ? r4
                   : (j == 2) ? r4 * r4
                              : r4 * r4 * r4;
        s.e0 = base * r; s.e1 = s.e0 * r; s.e2 = s.e1 * r; s.e3 = s.e2 * r;
    } else {
        s.e0 = __expf(dt * Aq[0]); s.e1 = __expf(dt * Aq[1]);
        s.e2 = __expf(dt * Aq[2]); s.e3 = __expf(dt * Aq[3]);
    }
    return s;
}

// ------------------------------ TF32 GEMM -----------------------------------
enum { EPI_INPROJ = 0, EPI_XPROJ = 1, EPI_OUTPROJ = 2, EPI_FC1 = 3, EPI_FC2 = 4 };

template <int EPI>
__global__ __launch_bounds__(256) void mma_gemm_kernel(
    const float* __restrict__ A, const float* __restrict__ W,
    const float* __restrict__ bias, const float* __restrict__ resid,
    float* __restrict__ out, int M, int N, int Kdim)
{
    constexpr int BM = 128, BN = 64, BK = 16;
    __shared__ uint32_t As[BK][BM + 8];
    __shared__ uint32_t Ws[BK][BN + 8];

    const int tid = threadIdx.x;
    const int m0 = blockIdx.y * BM;
    const int n0 = blockIdx.x * BN;

    size_t zbase = 0;
    const float* Wb = W;
    const float* Ab = A;
    if (EPI == EPI_XPROJ) {
        const int kz = blockIdx.z;
        zbase = (size_t)kz * (size_t)M;
        Wb = W + (size_t)kz * C38 * DIc;
        Ab = A + (size_t)((kz < 2) ? kz : (kz - 2)) * (size_t)M * Kdim;
    }

    const int lmA = tid >> 1;
    const int kA  = (tid & 1) * 8;
    const int lnW = tid >> 2;
    const int kW  = (tid & 3) * 4;

    int srow = m0 + lmA;
    if (EPI == EPI_XPROJ && blockIdx.z >= 2) {
        int tb = srow / LL;
        int l  = srow - tb * LL;
        srow = tb * LL + (LL - 1 - l);
    }
    const float* aptr = Ab + (size_t)srow * Kdim + kA;
    const float* wptr = Wb + (size_t)(n0 + lnW) * Kdim + kW;
    const bool wvalid = (n0 + lnW) < N;

    float4 av0 = *(const float4*)(aptr);
    float4 av1 = *(const float4*)(aptr + 4);
    float4 wv  = wvalid ? *(const float4*)(wptr) : make_float4(0.f, 0.f, 0.f, 0.f);

    const int wid = tid >> 5;
    const int wm  = wid & 3;
    const int wn  = wid >> 2;
    const int lane = tid & 31;
    const int gid = lane >> 2;
    const int tig = lane & 3;

    float acc[2][4][4];
#pragma unroll
    for (int i = 0; i < 2; i++)
#pragma unroll
        for (int j = 0; j < 4; j++)
#pragma unroll
            for (int q = 0; q < 4; q++) acc[i][j][q] = 0.0f;

    for (int kt = 0; kt < Kdim; kt += BK) {
        As[kA + 0][lmA] = f2tf32(av0.x); As[kA + 1][lmA] = f2tf32(av0.y);
        As[kA + 2][lmA] = f2tf32(av0.z); As[kA + 3][lmA] = f2tf32(av0.w);
        As[kA + 4][lmA] = f2tf32(av1.x); As[kA + 5][lmA] = f2tf32(av1.y);
        As[kA + 6][lmA] = f2tf32(av1.z); As[kA + 7][lmA] = f2tf32(av1.w);
        Ws[kW + 0][lnW] = f2tf32(wv.x);  Ws[kW + 1][lnW] = f2tf32(wv.y);
        Ws[kW + 2][lnW] = f2tf32(wv.z);  Ws[kW + 3][lnW] = f2tf32(wv.w);
        __syncthreads();

        if (kt + BK < Kdim) {
            av0 = *(const float4*)(aptr + kt + BK);
            av1 = *(const float4*)(aptr + kt + BK + 4);
            if (wvalid) wv = *(const float4*)(wptr + kt + BK);
        }

#pragma unroll
        for (int kc = 0; kc < BK; kc += 8) {
            uint32_t afr[2][4];
#pragma unroll
            for (int mt = 0; mt < 2; mt++) {
                const int mb = wm * 32 + mt * 16 + gid;
                afr[mt][0] = As[kc + tig    ][mb];
                afr[mt][1] = As[kc + tig    ][mb + 8];
                afr[mt][2] = As[kc + tig + 4][mb];
                afr[mt][3] = As[kc + tig + 4][mb + 8];
            }
            uint32_t bfr[4][2];
#pragma unroll
            for (int nt = 0; nt < 4; nt++) {
                const int nb = wn * 32 + nt * 8 + gid;
                bfr[nt][0] = Ws[kc + tig    ][nb];
                bfr[nt][1] = Ws[kc + tig + 4][nb];
            }
#pragma unroll
            for (int mt = 0; mt < 2; mt++)
#pragma unroll
                for (int nt = 0; nt < 4; nt++)
                    mma_tf32(acc[mt][nt], afr[mt], bfr[nt]);
        }
        __syncthreads();
    }

    auto store = [&](int gm, int gn, float v) {
        if (EPI == EPI_INPROJ) {
            if (gn < DIc)      g_xi[(size_t)gm * DIc + gn] = v;
            else               g_z [(size_t)gm * DIc + (gn - DIc)] = v;
        } else if (EPI == EPI_XPROJ) {
            if (gn < C38)      g_xdbl[(zbase + gm) * C38 + gn] = v;
        } else if (EPI == EPI_OUTPROJ) {
            if (gn < Cc)       g_xf2[(size_t)gm * Cc + gn] =
                                   resid[(size_t)gm * Cc + gn] + v;
        } else if (EPI == EPI_FC1) {
            g_h1[(size_t)gm * (4 * Cc) + gn] = gelu_exactf(v + bias[gn]);
        } else if (EPI == EPI_FC2) {
            if (gn < Cc)       out[(size_t)gm * Cc + gn] =
                                   g_xf2[(size_t)gm * Cc + gn] + v + bias[gn];
        }
    };

#pragma unroll
    for (int mt = 0; mt < 2; mt++) {
        const int r0 = m0 + wm * 32 + mt * 16 + gid;
#pragma unroll
        for (int nt = 0; nt < 4; nt++) {
            const int c0 = n0 + wn * 32 + nt * 8 + 2 * tig;
            store(r0,     c0,     acc[mt][nt][0]);
            store(r0,     c0 + 1, acc[mt][nt][1]);
            store(r0 + 8, c0,     acc[mt][nt][2]);
            store(r0 + 8, c0 + 1, acc[mt][nt][3]);
        }
    }
}

// --------------------- depthwise conv 3x3 + SiLU + cross-scan ---------------
__global__ __launch_bounds__(192) void conv_scan_kernel(
    const float* __restrict__ cw, const float* __restrict__ cb)
{
    const int tb = blockIdx.x / HH;
    const int h  = blockIdx.x % HH;
    const int d  = threadIdx.x;

    float wg[9];
#pragma unroll
    for (int i = 0; i < 9; i++) wg[i] = cw[d * 9 + i];
    const float bias = cb[d];

    const float* xin = g_xi + (size_t)tb * LL * DIc + d;

    float c0[3], c1[3], c2[3];
    auto loadcol = [&](int wc, float* col) {
#pragma unroll
        for (int r = 0; r < 3; r++) {
            int hh = h - 1 + r;
            col[r] = (hh >= 0 && hh < HH && wc >= 0 && wc < WW)
                     ? xin[(size_t)(hh * WW + wc) * DIc] : 0.0f;
        }
    };
    loadcol(-1, c0);
    loadcol(0, c1);

    for (int w = 0; w < WW; w++) {
        loadcol(w + 1, c2);
        float acc = bias;
        acc += c0[0] * wg[0] + c1[0] * wg[1] + c2[0] * wg[2];
        acc += c0[1] * wg[3] + c1[1] * wg[4] + c2[1] * wg[5];
        acc += c0[2] * wg[6] + c1[2] * wg[7] + c2[2] * wg[8];
        float v = siluf(acc);

        int lrm = h * WW + w;
        int lcm = w * HH + h;
        g_xs2[((size_t)(0 * TBc + tb) * LL + lrm) * DIc + d] = v;
        g_xs2[((size_t)(1 * TBc + tb) * LL + lcm) * DIc + d] = v;

        c0[0] = c1[0]; c0[1] = c1[1]; c0[2] = c1[2];
        c1[0] = c2[0]; c1[1] = c2[1]; c1[2] = c2[2];
    }
}

// ------------------------- chunked selective scan ---------------------------
// Channel c = kb*DIc + d (kb = k*16+tb). 4 lanes/channel, 4 states/lane.
// Segment seg covers scan positions [seg*SEG, (seg+1)*SEG).

struct ScanCtx {
    int j, c, seg, kb, d, kz, tb, n0;
    bool pow_ok;
    float Aq[4], wr[Rc], dbias;
    const float* up; int ustride;
    const float* rowp;
};

__device__ __forceinline__ ScanCtx scan_setup(
    int t, const float* A_logs, const float* dtw, const float* dtb)
{
    ScanCtx s;
    s.j   = t & 3;
    int cs = t >> 2;
    s.seg = cs / NCH;
    s.c   = cs - s.seg * NCH;
    s.kb  = s.c / DIc;
    s.d   = s.c - s.kb * DIc;
    s.kz  = s.kb >> 4;
    s.tb  = s.kb & 15;
    s.n0  = 4 * s.j;
    const int ad = s.kz * DIc + s.d;

#pragma unroll
    for (int i = 0; i < 4; i++) s.Aq[i] = -expf(A_logs[ad * NSc + s.n0 + i]);
    bool pw = true;
#pragma unroll
    for (int i = 0; i < 4; i++)
        pw = pw && (fabsf(s.Aq[i] + (float)(s.n0 + i + 1)) < 1e-5f);
    s.pow_ok = __all_sync(0xffffffffu, pw);

    const float* wp = dtw + ((size_t)s.kz * DIc + s.d) * Rc;
#pragma unroll
    for (int r = 0; r < Rc; r++) s.wr[r] = wp[r];
    s.dbias = dtb[s.kz * DIc + s.d];

    const int p0 = s.seg * SEG;
    if (s.kz < 2) {
        s.up = g_xs2 + ((size_t)(s.kz * TBc + s.tb) * LL + p0) * DIc + s.d;
        s.ustride = DIc;
    } else {
        s.up = g_xs2 + ((size_t)((s.kz - 2) * TBc + s.tb) * LL + (LL - 1 - p0)) * DIc + s.d;
        s.ustride = -DIc;
    }
    s.rowp = g_xdbl + ((size_t)s.kb * LL + p0) * C38;
    return s;
}

// pass 1: local scan per segment (h=0 init); emits h_end and decay product.
__global__ __launch_bounds__(256) void scan_pass1(
    const float* __restrict__ A_logs,
    const float* __restrict__ dtw, const float* __restrict__ dtb)
{
    const int t = blockIdx.x * 256 + threadIdx.x;
    ScanCtx s = scan_setup(t, A_logs, dtw, dtb);

    const float* up   = s.up;
    const float* rowp = s.rowp;
    float h0 = 0.f, h1 = 0.f, h2 = 0.f, h3 = 0.f;
    float E0 = 1.f, E1 = 1.f, E2 = 1.f, E3 = 1.f;

    for (int i = 0; i < SEG; i++) {
        float  u   = up[0];
        float2 x01 = *(const float2*)(rowp + 0);
        float2 x23 = *(const float2*)(rowp + 2);
        float2 x45 = *(const float2*)(rowp + 4);
        float2 B01 = *(const float2*)(rowp + 6 + s.n0);
        float2 B23 = *(const float2*)(rowp + 8 + s.n0);

        StepDecay sd = step_decay(x01, x23, x45, s.wr, s.dbias, s.pow_ok, s.j, s.Aq);
        float du = sd.dt * u;
        h0 = fmaf(h0, sd.e0, du * B01.x);
        h1 = fmaf(h1, sd.e1, du * B01.y);
        h2 = fmaf(h2, sd.e2, du * B23.x);
        h3 = fmaf(h3, sd.e3, du * B23.y);
        E0 *= sd.e0; E1 *= sd.e1; E2 *= sd.e2; E3 *= sd.e3;

        up += s.ustride; rowp += C38;
    }

    const size_t o = ((size_t)s.c * NSEG + s.seg) * NSc + s.n0;
    g_hend[o + 0] = h0; g_hend[o + 1] = h1; g_hend[o + 2] = h2; g_hend[o + 3] = h3;
    g_Eend[o + 0] = E0; g_Eend[o + 1] = E1; g_Eend[o + 2] = E2; g_Eend[o + 3] = E3;
}

// prefix: sequential over NSEG segments per (channel, state-quad).
__global__ __launch_bounds__(256) void scan_prefix()
{
    const int t = blockIdx.x * 256 + threadIdx.x;   // 49152 threads
    const int j = t & 3;
    const int c = t >> 2;
    const int n0 = 4 * j;
    const size_t base = (size_t)c * NSEG * NSc + n0;

    float h0 = 0.f, h1 = 0.f, h2 = 0.f, h3 = 0.f;
    g_h0[base + 0] = 0.f; g_h0[base + 1] = 0.f;
    g_h0[base + 2] = 0.f; g_h0[base + 3] = 0.f;

    for (int sg = 0; sg < NSEG - 1; sg++) {
        const size_t o = base + (size_t)sg * NSc;
        h0 = fmaf(h0, g_Eend[o + 0], g_hend[o + 0]);
        h1 = fmaf(h1, g_Eend[o + 1], g_hend[o + 1]);
        h2 = fmaf(h2, g_Eend[o + 2], g_hend[o + 2]);
        h3 = fmaf(h3, g_Eend[o + 3], g_hend[o + 3]);
        const size_t on = o + NSc;
        g_h0[on + 0] = h0; g_h0[on + 1] = h1;
        g_h0[on + 2] = h2; g_h0[on + 3] = h3;
    }
}

// pass 2: full scan per segment with correct initial state; writes y (+D skip).
__global__ __launch_bounds__(256) void scan_pass2(
    const float* __restrict__ A_logs, const float* __restrict__ Ds,
    const float* __restrict__ dtw, const float* __restrict__ dtb)
{
    const int t = blockIdx.x * 256 + threadIdx.x;
    ScanCtx s = scan_setup(t, A_logs, dtw, dtb);
    const float Dv = Ds[s.kz * DIc + s.d];

    const size_t o = ((size_t)s.c * NSEG + s.seg) * NSc + s.n0;
    float h0 = g_h0[o + 0], h1 = g_h0[o + 1];
    float h2 = g_h0[o + 2], h3 = g_h0[o + 3];

    const float* up   = s.up;
    const float* rowp = s.rowp;
    float* yp = g_ysT + ((size_t)s.kb * LL + s.seg * SEG) * DIc + s.d;

    for (int i = 0; i < SEG; i++) {
        float  u   = up[0];
        float2 x01 = *(const float2*)(rowp + 0);
        float2 x23 = *(const float2*)(rowp + 2);
        float2 x45 = *(const float2*)(rowp + 4);
        float2 B01 = *(const float2*)(rowp + 6 + s.n0);
        float2 B23 = *(const float2*)(rowp + 8 + s.n0);
        float2 C01 = *(const float2*)(rowp + 22 + s.n0);
        float2 C23 = *(const float2*)(rowp + 24 + s.n0);

        StepDecay sd = step_decay(x01, x23, x45, s.wr, s.dbias, s.pow_ok, s.j, s.Aq);
        float du = sd.dt * u;
        h0 = fmaf(h0, sd.e0, du * B01.x);
        h1 = fmaf(h1, sd.e1, du * B01.y);
        h2 = fmaf(h2, sd.e2, du * B23.x);
        h3 = fmaf(h3, sd.e3, du * B23.y);

        float acc = h0 * C01.x + h1 * C01.y + h2 * C23.x + h3 * C23.y;
        acc += __shfl_xor_sync(0xffffffffu, acc, 1);
        acc += __shfl_xor_sync(0xffffffffu, acc, 2);
        if (s.j == 0) yp[0] = acc + Dv * u;

        up += s.ustride; rowp += C38; yp += DIc;
    }
}

// ----------------- cross-merge + LayerNorm + SiLU gate ----------------------
__global__ __launch_bounds__(192) void merge_ln_gate_kernel(
    const float* __restrict__ ln_g, const float* __restrict__ ln_b)
{
    const int bid = blockIdx.x;
    const int tb  = bid / LL;
    const int l   = bid % LL;
    const int d   = threadIdx.x;
    const int h   = l / WW, w = l % WW;
    const int l2  = w * HH + h;

    float y = g_ysT[((size_t)(0 * TBc + tb) * LL + l)             * DIc + d]
            + g_ysT[((size_t)(1 * TBc + tb) * LL + l2)            * DIc + d]
            + g_ysT[((size_t)(2 * TBc + tb) * LL + (LL - 1 - l))  * DIc + d]
            + g_ysT[((size_t)(3 * TBc + tb) * LL + (LL - 1 - l2)) * DIc + d];

    float s = y, s2 = y * y;
#pragma unroll
    for (int o = 16; o > 0; o >>= 1) {
        s  += __shfl_xor_sync(0xffffffffu, s,  o);
        s2 += __shfl_xor_sync(0xffffffffu, s2, o);
    }
    __shared__ float sh[14];
    const int wid = d >> 5;
    if ((d & 31) == 0) { sh[wid] = s; sh[6 + wid] = s2; }
    __syncthreads();
    if (d == 0) {
        float ts = 0.f, ts2 = 0.f;
#pragma unroll
        for (int i = 0; i < 6; i++) { ts += sh[i]; ts2 += sh[6 + i]; }
        float mu  = ts * (1.0f / 192.0f);
        float var = ts2 * (1.0f / 192.0f) - mu * mu;
        sh[12] = mu;
        sh[13] = rsqrtf(var + 1e-5f);
    }
    __syncthreads();
    float mu = sh[12], rs = sh[13];

    float yn = (y - mu) * rs * ln_g[d] + ln_b[d];
    size_t zi = ((size_t)tb * LL + l) * DIc + d;
    float zv = g_z[zi];
    g_y[zi] = yn * siluf(zv);
}

// ------------------------------- launch -------------------------------------
extern "C" void kernel_launch(void* const* d_in, const int* in_sizes, int n_in,
                              void* d_out, int out_size)
{
    const float* x          = (const float*)d_in[0];
    const float* in_proj_w  = (const float*)d_in[1];
    const float* conv_w     = (const float*)d_in[2];
    const float* conv_b     = (const float*)d_in[3];
    const float* x_proj_w   = (const float*)d_in[4];
    const float* dt_w       = (const float*)d_in[5];
    const float* dt_b       = (const float*)d_in[6];
    const float* A_logs     = (const float*)d_in[7];
    const float* Ds         = (const float*)d_in[8];
    const float* ln_g       = (const float*)d_in[9];
    const float* ln_b       = (const float*)d_in[10];
    const float* out_proj_w = (const float*)d_in[11];
    const float* fc1_w      = (const float*)d_in[12];
    const float* fc1_b      = (const float*)d_in[13];
    const float* fc2_w      = (const float*)d_in[14];
    const float* fc2_b      = (const float*)d_in[15];
    float* out = (float*)d_out;

    float *pxs2 = nullptr, *py = nullptr, *pxf2 = nullptr, *ph1 = nullptr;
    cudaGetSymbolAddress((void**)&pxs2, g_xs2);
    cudaGetSymbolAddress((void**)&py,   g_y);
    cudaGetSymbolAddress((void**)&pxf2, g_xf2);
    cudaGetSymbolAddress((void**)&ph1,  g_h1);

    // 1. in_proj: (50176 x 96) @ (384 x 96)^T -> xi | z
    mma_gemm_kernel<EPI_INPROJ><<<dim3(6, M1c / 128), 256>>>(
        x, in_proj_w, nullptr, nullptr, nullptr, M1c, 384, Cc);

    // 2. depthwise conv + SiLU + cross-scan (dirs 0,1 only)
    conv_scan_kernel<<<TBc * HH, 192>>>(conv_w, conv_b);

    // 3. x_proj: per-direction (50176 x 192) @ (38 x 192)^T -> dts|B|C
    mma_gemm_kernel<EPI_XPROJ><<<dim3(1, M1c / 128, Kc), 256>>>(
        pxs2, x_proj_w, nullptr, nullptr, nullptr, M1c, C38, DIc);

    // 4. chunked selective scan: local pass, prefix, final pass
    const int scan_threads = NCH * 4 * NSEG;      // 786432
    scan_pass1<<<scan_threads / 256, 256>>>(A_logs, dt_w, dt_b);
    scan_prefix<<<(NCH * 4) / 256, 256>>>();
    scan_pass2<<<scan_threads / 256, 256>>>(A_logs, Ds, dt_w, dt_b);

    // 5. cross-merge + LayerNorm + SiLU(z) gate
    merge_ln_gate_kernel<<<TBc * LL, 192>>>(ln_g, ln_b);

    // 6. out_proj + residual 1 -> g_xf2
    mma_gemm_kernel<EPI_OUTPROJ><<<dim3(2, M1c / 128), 256>>>(
        py, out_proj_w, nullptr, x, nullptr, M1c, Cc, DIc);

    // 7. fc1 + bias + exact GELU -> g_h1
    mma_gemm_kernel<EPI_FC1><<<dim3(6, M1c / 128), 256>>>(
        pxf2, fc1_w, fc1_b, nullptr, nullptr, M1c, 4 * Cc, Cc);

    // 8. fc2 + bias + residual 2 -> d_out
    mma_gemm_kernel<EPI_FC2><<<dim3(2, M1c / 128), 256>>>(
        ph1, fc2_w, fc2_b, nullptr, out, M1c, Cc, 4 * Cc);
}